// round 3
// baseline (speedup 1.0000x reference)
#include <cuda_runtime.h>
#include <math.h>

#define B_ 64
#define L_ 128
#define E_ 512
#define N_ 512
#define H_ 1024
#define G3 3072
#define KA 1536   /* E+H */
#define SA 6      /* split-K for gx gemm (K=1536, Kc=256) */
#define SB 4      /* split-K for gh gemm (K=1024, Kc=256) */
#define SQ 8      /* split-K for q gemm  (K=1024, Kc=128) */
#define SF 8      /* split-K for final gemm (K=2048, Kc=256) */
#define NBLK 148
#define NTHR 256

// ---------------- device scratch (static, no allocations) ----------------
__device__ float g_keys[(size_t)B_ * N_ * H_];   // 134 MB
__device__ float g_h[B_ * H_];
__device__ float g_xg1[B_ * KA];                 // [emb_t | h]
__device__ float g_xf[B_ * 2 * H_];              // [rnn_out | context]
__device__ float g_score[B_ * N_];
__device__ float g_attn[B_ * N_];
__device__ float g_gxp[SA * B_ * G3];
__device__ float g_ghp[SB * B_ * G3];
__device__ float g_qp[SQ * B_ * H_];
__device__ float g_fp[SF * B_ * H_];
__device__ unsigned g_cnt;   // zero-init, returns to 0 after every launch
__device__ unsigned g_gen;   // monotone generation counter (wrap-safe compare)

__device__ __forceinline__ float tanh_fast(float x) {
    float y;
    asm("tanh.approx.f32 %0, %1;" : "=f"(y) : "f"(x));
    return y;
}

// ---------------- software grid barrier (all NBLK CTAs co-resident) ----------------
__device__ __forceinline__ void gbar(unsigned& target, int nb) {
    __syncthreads();
    if (threadIdx.x == 0) {
        __threadfence();
        unsigned v = atomicAdd(&g_cnt, 1u);
        if (v == (unsigned)nb - 1u) {
            atomicExch(&g_cnt, 0u);
            __threadfence();
            atomicAdd(&g_gen, 1u);
        } else {
            while ((int)(*(volatile unsigned*)&g_gen - target) < 0) __nanosleep(64);
        }
        target++;
    }
    __syncthreads();
}

// ---------------- 64x64 split-K SGEMM tile ----------------
// Cp[(s*M + m0+row)*Nn + n0+col] = sum_{k in [k0,k0+Kc)} A[m0+row, k] * W[n0+col, k]
__device__ __forceinline__ void gemm_tile(
    const float* __restrict__ A, int lda,
    const float* __restrict__ W, int ldw,
    float* __restrict__ Cp, int M, int Nn,
    int m0, int n0, int k0, int Kc, int s, float* sm)
{
    float (*As)[68] = (float(*)[68])sm;
    float (*Ws)[68] = (float(*)[68])(sm + 16 * 68);
    const int tid = threadIdx.x;
    const int tx = tid & 15, ty = tid >> 4;
    const int lr = tid >> 2, lk = (tid & 3) << 2;

    float acc[4][4] = {};
    const float* Ap = A + (size_t)(m0 + lr) * lda + k0 + lk;
    const float* Wp = W + (size_t)(n0 + lr) * ldw + k0 + lk;

    for (int kt = 0; kt < Kc; kt += 16) {
        float4 av = *(const float4*)(Ap + kt);
        float4 wv = *(const float4*)(Wp + kt);
        __syncthreads();
        As[lk + 0][lr] = av.x; As[lk + 1][lr] = av.y;
        As[lk + 2][lr] = av.z; As[lk + 3][lr] = av.w;
        Ws[lk + 0][lr] = wv.x; Ws[lk + 1][lr] = wv.y;
        Ws[lk + 2][lr] = wv.z; Ws[lk + 3][lr] = wv.w;
        __syncthreads();
#pragma unroll
        for (int kk = 0; kk < 16; kk++) {
            float4 a = *(const float4*)&As[kk][ty << 2];
            float4 w = *(const float4*)&Ws[kk][tx << 2];
            acc[0][0] += a.x * w.x; acc[0][1] += a.x * w.y; acc[0][2] += a.x * w.z; acc[0][3] += a.x * w.w;
            acc[1][0] += a.y * w.x; acc[1][1] += a.y * w.y; acc[1][2] += a.y * w.z; acc[1][3] += a.y * w.w;
            acc[2][0] += a.z * w.x; acc[2][1] += a.z * w.y; acc[2][2] += a.z * w.z; acc[2][3] += a.z * w.w;
            acc[3][0] += a.w * w.x; acc[3][1] += a.w * w.y; acc[3][2] += a.w * w.z; acc[3][3] += a.w * w.w;
        }
    }
#pragma unroll
    for (int i = 0; i < 4; i++) {
        float4 o = make_float4(acc[i][0], acc[i][1], acc[i][2], acc[i][3]);
        *(float4*)&Cp[((size_t)s * M + m0 + (ty << 2) + i) * Nn + n0 + (tx << 2)] = o;
    }
}

// ---------------- the one persistent kernel ----------------
__global__ __launch_bounds__(NTHR, 1) void decoder_all(
    const float* __restrict__ emb,   const float* __restrict__ value,
    const float* __restrict__ vmask, const float* __restrict__ state,
    const float* __restrict__ W_ih,  const float* __restrict__ b_ih,
    const float* __restrict__ W_hh,  const float* __restrict__ b_hh,
    const float* __restrict__ Wq,    const float* __restrict__ Wk,
    const float* __restrict__ v_att, const float* __restrict__ Wm,
    const float* __restrict__ bm,
    float* __restrict__ out, float* __restrict__ attn_out)
{
    __shared__ float sm[2176];   // gemm: 2*16*68; score: 2*H_; ctx: N_; softmax: 16
    const int bid = blockIdx.x, nb = gridDim.x, tid = threadIdx.x;
    unsigned target = 0;
    if (tid == 0) target = *(volatile unsigned*)&g_gen + 1u;

    // ---- phase 0: init h/xg1 + keys GEMM ----
    for (int i = bid * NTHR + tid; i < B_ * H_; i += nb * NTHR) {
        int b = i >> 10, j = i & 1023;
        float v = state[i];
        g_h[i] = v;
        g_xg1[b * KA + E_ + j] = v;
    }
    for (int i = bid * NTHR + tid; i < B_ * E_; i += nb * NTHR) {
        int b = i >> 9, e = i & 511;
        g_xg1[b * KA + e] = emb[(size_t)b * L_ * E_ + e];   // t = 0
    }
    // keys[b,n,k] = sum_h value[b,n,h] * Wk[k,h]  (M=B*N=32768, Nn=H, K=H)
    for (int u = bid; u < (B_ * N_ / 64) * (H_ / 64); u += nb) {
        int mt = u >> 4, nt = u & 15;
        gemm_tile(value, H_, Wk, H_, g_keys, B_ * N_, H_, mt * 64, nt * 64, 0, H_, 0, sm);
    }
    gbar(target, nb);

    for (int t = 0; t < L_; t++) {
        // ---- P1: gx = [emb|h] @ W_ih^T  (288 units)  +  gh = h @ W_hh^T (192 units) ----
        for (int u = bid; u < 288 + 192; u += nb) {
            if (u < 288) {
                int nt = u % 48, s = u / 48;
                gemm_tile(g_xg1, KA, W_ih, KA, g_gxp, B_, G3, 0, nt * 64, s * 256, 256, s, sm);
            } else {
                int u2 = u - 288;
                int nt = u2 % 48, s = u2 / 48;
                gemm_tile(g_h, H_, W_hh, H_, g_ghp, B_, G3, 0, nt * 64, s * 256, 256, s, sm);
            }
        }
        gbar(target, nb);

        // ---- P2: GRU elementwise ----
        for (int i = bid * NTHR + tid; i < B_ * H_; i += nb * NTHR) {
            int b = i >> 10, j = i & 1023;
            float gxr = 0.f, gxz = 0.f, gxn = 0.f, ghr = 0.f, ghz = 0.f, ghn = 0.f;
#pragma unroll
            for (int s = 0; s < SA; s++) {
                const float* p = &g_gxp[((size_t)s * B_ + b) * G3];
                gxr += p[j]; gxz += p[H_ + j]; gxn += p[2 * H_ + j];
            }
#pragma unroll
            for (int s = 0; s < SB; s++) {
                const float* p = &g_ghp[((size_t)s * B_ + b) * G3];
                ghr += p[j]; ghz += p[H_ + j]; ghn += p[2 * H_ + j];
            }
            float r = 1.f / (1.f + expf(-(gxr + b_ih[j]        + ghr + b_hh[j])));
            float z = 1.f / (1.f + expf(-(gxz + b_ih[H_ + j]   + ghz + b_hh[H_ + j])));
            float n = tanhf(gxn + b_ih[2 * H_ + j] + r * (ghn + b_hh[2 * H_ + j]));
            float h = g_h[i];
            g_xf[b * 2 * H_ + j] = (1.f - z) * n + z * h;
        }
        gbar(target, nb);

        // ---- P3: q = rnn @ Wq^T (128 units) + final-gemm rnn-half (64 units) ----
        for (int u = bid; u < 192; u += nb) {
            if (u < 128) {
                int nt = u & 15, s = u >> 4;
                gemm_tile(g_xf, 2 * H_, Wq, H_, g_qp, B_, H_, 0, nt * 64, s * 128, 128, s, sm);
            } else {
                int u2 = u - 128;
                int nt = u2 & 15, s = u2 >> 4;   // s in 0..3 -> k in [0,1024): rnn part
                gemm_tile(g_xf, 2 * H_, Wm, 2 * H_, g_fp, B_, H_, 0, nt * 64, s * 256, 256, s, sm);
            }
        }
        gbar(target, nb);

        // ---- P4: score (256 units of (b, n-chunk of 128)) ----
        for (int u = bid; u < B_ * 4; u += nb) {
            int b = u >> 2, c = u & 3;
            __syncthreads();
            for (int j = tid; j < H_; j += NTHR) {
                float a = 0.f;
#pragma unroll
                for (int s = 0; s < SQ; s++) a += g_qp[((size_t)s * B_ + b) * H_ + j];
                sm[j] = a;
                sm[H_ + j] = v_att[j];
            }
            __syncthreads();
            int w = tid >> 5, lane = tid & 31;
            const float4* qv4 = (const float4*)sm;
            const float4* vv4 = (const float4*)(sm + H_);
            for (int i = 0; i < 16; i++) {
                int n = c * 128 + w * 16 + i;
                const float4* kp = (const float4*)&g_keys[(size_t)(b * N_ + n) * H_];
                float acc = 0.f;
#pragma unroll
                for (int v8 = 0; v8 < 8; v8++) {
                    float4 kv = kp[lane + 32 * v8];
                    float4 q4 = qv4[lane + 32 * v8];
                    float4 vv = vv4[lane + 32 * v8];
                    acc += vv.x * tanh_fast(q4.x + kv.x);
                    acc += vv.y * tanh_fast(q4.y + kv.y);
                    acc += vv.z * tanh_fast(q4.z + kv.z);
                    acc += vv.w * tanh_fast(q4.w + kv.w);
                }
#pragma unroll
                for (int o = 16; o; o >>= 1) acc += __shfl_xor_sync(0xffffffffu, acc, o);
                if (lane == 0) {
                    float mk = vmask[b * N_ + n];
                    g_score[b * N_ + n] = (mk > 0.f) ? acc : -1e9f;
                }
            }
        }
        gbar(target, nb);

        // ---- P5: softmax (64 units, 256 threads handle 512 cols) ----
        for (int u = bid; u < B_; u += nb) {
            __syncthreads();
            int b = u;
            float s0 = g_score[b * N_ + tid];
            float s1 = g_score[b * N_ + 256 + tid];
            float m = fmaxf(s0, s1);
#pragma unroll
            for (int o = 16; o; o >>= 1) m = fmaxf(m, __shfl_xor_sync(0xffffffffu, m, o));
            if ((tid & 31) == 0) sm[tid >> 5] = m;
            __syncthreads();
            float M = fmaxf(fmaxf(fmaxf(sm[0], sm[1]), fmaxf(sm[2], sm[3])),
                            fmaxf(fmaxf(sm[4], sm[5]), fmaxf(sm[6], sm[7])));
            float p0 = expf(s0 - M), p1 = expf(s1 - M);
            float ss = p0 + p1;
#pragma unroll
            for (int o = 16; o; o >>= 1) ss += __shfl_xor_sync(0xffffffffu, ss, o);
            if ((tid & 31) == 0) sm[8 + (tid >> 5)] = ss;
            __syncthreads();
            float Z = (sm[8] + sm[9] + sm[10] + sm[11]) + (sm[12] + sm[13] + sm[14] + sm[15]);
            float inv = 1.f / Z;
            float a0 = p0 * inv, a1 = p1 * inv;
            g_attn[b * N_ + tid] = a0;
            g_attn[b * N_ + 256 + tid] = a1;
            attn_out[((size_t)b * L_ + t) * N_ + tid] = a0;
            attn_out[((size_t)b * L_ + t) * N_ + 256 + tid] = a1;
        }
        gbar(target, nb);

        // ---- P6: context (256 units of (b, h-chunk of 256)) ----
        for (int u = bid; u < B_ * 4; u += nb) {
            __syncthreads();
            int b = u >> 2, hb = u & 3;
            sm[tid] = g_attn[b * N_ + tid];
            sm[256 + tid] = g_attn[b * N_ + 256 + tid];
            __syncthreads();
            int h = hb * 256 + tid;
            const float* vp = &value[(size_t)b * N_ * H_ + h];
            float acc = 0.f;
#pragma unroll 8
            for (int n = 0; n < N_; n++) acc += sm[n] * vp[(size_t)n * H_];
            g_xf[b * 2 * H_ + H_ + h] = acc;
        }
        gbar(target, nb);

        // ---- P7: final-gemm ctx-half (64 units, s in 4..7 -> k in [1024,2048)) ----
        for (int u = bid; u < 64; u += nb) {
            int nt = u & 15, s = 4 + (u >> 4);
            gemm_tile(g_xf, 2 * H_, Wm, 2 * H_, g_fp, B_, H_, 0, nt * 64, s * 256, 256, s, sm);
        }
        gbar(target, nb);

        // ---- P8: final elementwise + stage next emb ----
        for (int i = bid * NTHR + tid; i < B_ * H_; i += nb * NTHR) {
            int b = i >> 10, j = i & 1023;
            float a = bm[j];
#pragma unroll
            for (int s = 0; s < SF; s++) a += g_fp[((size_t)s * B_ + b) * H_ + j];
            float y = tanhf(a);
            out[((size_t)b * L_ + t) * H_ + j] = y;
            g_h[i] = y;
            g_xg1[b * KA + E_ + j] = y;
        }
        if (t + 1 < L_) {
            for (int i = bid * NTHR + tid; i < B_ * E_; i += nb * NTHR) {
                int b = i >> 9, e = i & 511;
                g_xg1[b * KA + e] = emb[((size_t)b * L_ + t + 1) * E_ + e];
            }
        }
        gbar(target, nb);
    }
}

// ---------------- launch: ONE graph node ----------------
extern "C" void kernel_launch(void* const* d_in, const int* in_sizes, int n_in,
                              void* d_out, int out_size) {
    const float* emb    = (const float*)d_in[0];
    const float* value  = (const float*)d_in[1];
    const float* vmask  = (const float*)d_in[2];
    const float* state  = (const float*)d_in[3];
    const float* W_ih   = (const float*)d_in[4];
    const float* b_ih   = (const float*)d_in[5];
    const float* W_hh   = (const float*)d_in[6];
    const float* b_hh   = (const float*)d_in[7];
    const float* Wq     = (const float*)d_in[8];
    const float* Wk     = (const float*)d_in[9];
    const float* v_att  = (const float*)d_in[10];
    const float* Wm     = (const float*)d_in[11];
    const float* bm     = (const float*)d_in[12];

    float* out      = (float*)d_out;                 // outputs: B x L x H
    float* attn_out = out + (size_t)B_ * L_ * H_;    // attns:   B x L x N

    decoder_all<<<NBLK, NTHR>>>(emb, value, vmask, state, W_ih, b_ih, W_hh, b_hh,
                                Wq, Wk, v_att, Wm, bm, out, attn_out);
}

// round 4
// speedup vs baseline: 1.6348x; 1.6348x over previous
#include <cuda_runtime.h>
#include <math.h>

#define B_ 64
#define L_ 128
#define E_ 512
#define N_ 512
#define H_ 1024
#define G3 3072
#define KA 1536
#define NBLK 148
#define NTHR 512

#define SA 24   /* gx splits, Kc=64  (K=1536) */
#define SB 16   /* gh splits, Kc=64  (K=1024) */
#define SQ 8    /* q  splits, Kc=128 (K=1024) */
#define SF 24   /* final: s 0..7 rnn-half (Kc=128) + s 8..23 ctx-half (Kc=64) */

// ---------------- device scratch (static, no allocations) ----------------
__device__ float g_keys[(size_t)B_ * N_ * H_];
__device__ float g_h[B_ * H_];
__device__ float g_xg1[B_ * KA];
__device__ float g_xf[B_ * 2 * H_];
__device__ float g_score[B_ * N_];
__device__ float g_attn[B_ * N_];
__device__ float g_gxp[(size_t)SA * B_ * G3];
__device__ float g_ghp[(size_t)SB * B_ * G3];
__device__ float g_qp[(size_t)SQ * B_ * H_];
__device__ float g_fp[(size_t)SF * B_ * H_];
__device__ unsigned g_cnt;
__device__ unsigned g_gen;
__device__ unsigned g_q[4];   // work-queue counters (0: keys, 1: P1, 2: P4)

__device__ __forceinline__ float tanh_fast(float x) {
    float y;
    asm("tanh.approx.f32 %0, %1;" : "=f"(y) : "f"(x));
    return y;
}

// ---------------- grid barrier; winner optionally resets a queue counter ----------------
__device__ __forceinline__ void gbar(unsigned& target, int resetq) {
    __syncthreads();
    if (threadIdx.x == 0) {
        __threadfence();
        if (atomicAdd(&g_cnt, 1u) == (unsigned)NBLK - 1u) {
            atomicExch(&g_cnt, 0u);
            if (resetq >= 0) atomicExch(&g_q[resetq], 0u);
            __threadfence();
            atomicAdd(&g_gen, 1u);
        } else {
            while ((int)(*(volatile unsigned*)&g_gen - target) < 0) __nanosleep(32);
        }
        target++;
    }
    __syncthreads();
}

__device__ __forceinline__ int qfetch(int c, int* s_u) {
    __syncthreads();
    if (threadIdx.x == 0) *s_u = (int)atomicAdd(&g_q[c], 1u);
    __syncthreads();
    return *s_u;
}

// ---------------- 64(M) x 128(N) x Kc SGEMM tile, double-buffered ----------------
// Co[m*ldc + n] = sum_{k<Kc} Ap[m*lda + k] * Wp[n*ldw + k]
__device__ __forceinline__ void gemm_tile(
    const float* __restrict__ Ap, int lda,
    const float* __restrict__ Wp, int ldw,
    float* __restrict__ Co, int ldc,
    int Kc, float* sm)
{
    const int tid = threadIdx.x;
    const int am = tid >> 3, ak = (tid & 7) << 1;     // A stage: 64 x 16 via float2
    const int wn = tid >> 2, wk = (tid & 3) << 2;     // W stage: 128 x 16 via float4
    const int tx = tid & 31, ty = tid >> 5;           // micro: 4m x 4n
    const int nkt = Kc >> 4;

    float acc[4][4] = {};
    float2 areg = *(const float2*)(Ap + (size_t)am * lda + ak);
    float4 wreg = *(const float4*)(Wp + (size_t)wn * ldw + wk);

    __syncthreads();   // protect smem buffers from previous use
    for (int kt = 0; kt < nkt; kt++) {
        float* As = sm + (kt & 1) * 3200;
        float* Ws = As + 1088;
        As[(ak + 0) * 68 + am] = areg.x;
        As[(ak + 1) * 68 + am] = areg.y;
        Ws[(wk + 0) * 132 + wn] = wreg.x;
        Ws[(wk + 1) * 132 + wn] = wreg.y;
        Ws[(wk + 2) * 132 + wn] = wreg.z;
        Ws[(wk + 3) * 132 + wn] = wreg.w;
        if (kt + 1 < nkt) {
            areg = *(const float2*)(Ap + (size_t)am * lda + (kt + 1) * 16 + ak);
            wreg = *(const float4*)(Wp + (size_t)wn * ldw + (kt + 1) * 16 + wk);
        }
        __syncthreads();
#pragma unroll
        for (int kk = 0; kk < 16; kk++) {
            float4 a = *(const float4*)(As + kk * 68 + (ty << 2));
            float4 w = *(const float4*)(Ws + kk * 132 + (tx << 2));
            acc[0][0] += a.x * w.x; acc[0][1] += a.x * w.y; acc[0][2] += a.x * w.z; acc[0][3] += a.x * w.w;
            acc[1][0] += a.y * w.x; acc[1][1] += a.y * w.y; acc[1][2] += a.y * w.z; acc[1][3] += a.y * w.w;
            acc[2][0] += a.z * w.x; acc[2][1] += a.z * w.y; acc[2][2] += a.z * w.z; acc[2][3] += a.z * w.w;
            acc[3][0] += a.w * w.x; acc[3][1] += a.w * w.y; acc[3][2] += a.w * w.z; acc[3][3] += a.w * w.w;
        }
    }
#pragma unroll
    for (int i = 0; i < 4; i++) {
        *(float4*)(Co + (size_t)((ty << 2) + i) * ldc + (tx << 2)) =
            make_float4(acc[i][0], acc[i][1], acc[i][2], acc[i][3]);
    }
}

// ---------------- the one persistent kernel ----------------
__global__ __launch_bounds__(NTHR, 1) void decoder_all(
    const float* __restrict__ emb,   const float* __restrict__ value,
    const float* __restrict__ vmask, const float* __restrict__ state,
    const float* __restrict__ W_ih,  const float* __restrict__ b_ih,
    const float* __restrict__ W_hh,  const float* __restrict__ b_hh,
    const float* __restrict__ Wq,    const float* __restrict__ Wk,
    const float* __restrict__ v_att, const float* __restrict__ Wm,
    const float* __restrict__ bm,
    float* __restrict__ out, float* __restrict__ attn_out)
{
    __shared__ float sm[6400];   // 2 x (16x68 A + 16x132 W) = 25.6 KB; reused by score/ctx
    __shared__ float red[32];
    __shared__ int   s_u;
    const int bid = blockIdx.x, tid = threadIdx.x;
    unsigned target = 0;
    if (tid == 0) target = *(volatile unsigned*)&g_gen + 1u;
    __syncthreads();

    // ---- phase 0: init h / xg1 + keys GEMM (queue 0) ----
    {
        int i = bid * NTHR + tid;
        if (i < B_ * H_) {
            int b = i >> 10, j = i & 1023;
            float v = state[i];
            g_h[i] = v;
            g_xg1[b * KA + E_ + j] = v;
        }
        if (i < B_ * E_) {
            int b = i >> 9, e = i & 511;
            g_xg1[b * KA + e] = emb[(size_t)b * L_ * E_ + e];   // t=0
        }
    }
    for (;;) {
        int u = qfetch(0, &s_u);
        if (u >= 512 * 8) break;
        int mt = u >> 3, nt = u & 7;
        gemm_tile(value + (size_t)mt * 64 * H_, H_,
                  Wk + (size_t)nt * 128 * H_, H_,
                  g_keys + (size_t)mt * 64 * H_ + nt * 128, H_, H_, sm);
    }
    gbar(target, 0);

    for (int t = 0; t < L_; t++) {
        // ---- P1: gx (576 units) + gh (384 units), Kc=64, queue 1 ----
        for (;;) {
            int u = qfetch(1, &s_u);
            if (u >= 960) break;
            if (u < 576) {
                int nt = u % 24, s = u / 24;
                gemm_tile(g_xg1 + s * 64, KA,
                          W_ih + (size_t)nt * 128 * KA + s * 64, KA,
                          g_gxp + (size_t)s * B_ * G3 + nt * 128, G3, 64, sm);
            } else {
                int u2 = u - 576;
                int nt = u2 % 24, s = u2 / 24;
                gemm_tile(g_h + s * 64, H_,
                          W_hh + (size_t)nt * 128 * H_ + s * 64, H_,
                          g_ghp + (size_t)s * B_ * G3 + nt * 128, G3, 64, sm);
            }
        }
        gbar(target, 1);

        // ---- P2: GRU elementwise ----
        {
            int i = bid * NTHR + tid;
            if (i < B_ * H_) {
                int b = i >> 10, j = i & 1023;
                float gxr = 0.f, gxz = 0.f, gxn = 0.f, ghr = 0.f, ghz = 0.f, ghn = 0.f;
#pragma unroll
                for (int s = 0; s < SA; s++) {
                    const float* p = &g_gxp[((size_t)s * B_ + b) * G3];
                    gxr += p[j]; gxz += p[H_ + j]; gxn += p[2 * H_ + j];
                }
#pragma unroll
                for (int s = 0; s < SB; s++) {
                    const float* p = &g_ghp[((size_t)s * B_ + b) * G3];
                    ghr += p[j]; ghz += p[H_ + j]; ghn += p[2 * H_ + j];
                }
                float r = 1.f / (1.f + expf(-(gxr + b_ih[j]        + ghr + b_hh[j])));
                float z = 1.f / (1.f + expf(-(gxz + b_ih[H_ + j]   + ghz + b_hh[H_ + j])));
                float n = tanhf(gxn + b_ih[2 * H_ + j] + r * (ghn + b_hh[2 * H_ + j]));
                float h = g_h[i];
                g_xf[b * 2 * H_ + j] = (1.f - z) * n + z * h;
            }
        }
        gbar(target, -1);

        // ---- P3: q (64 units, Kc=128) + final rnn-half (64 units, Kc=128), static ----
        if (bid < 128) {
            int u = bid;
            if (u < 64) {
                int nt = u & 7, s = u >> 3;
                gemm_tile(g_xf + s * 128, 2 * H_,
                          Wq + (size_t)nt * 128 * H_ + s * 128, H_,
                          g_qp + (size_t)s * B_ * H_ + nt * 128, H_, 128, sm);
            } else {
                int u2 = u - 64;
                int nt = u2 & 7, s = u2 >> 3;
                gemm_tile(g_xf + s * 128, 2 * H_,
                          Wm + (size_t)nt * 128 * 2 * H_ + s * 128, 2 * H_,
                          g_fp + (size_t)s * B_ * H_ + nt * 128, H_, 128, sm);
            }
        }
        gbar(target, -1);

        // ---- P4: score (256 units of (b, 128-n chunk)), queue 2 ----
        for (;;) {
            int u = qfetch(2, &s_u);
            if (u >= B_ * 4) break;
            int b = u >> 2, c = u & 3;
            for (int j = tid; j < H_; j += NTHR) {
                float a = 0.f;
#pragma unroll
                for (int s = 0; s < SQ; s++) a += g_qp[((size_t)s * B_ + b) * H_ + j];
                sm[j] = a;
                sm[H_ + j] = v_att[j];
            }
            __syncthreads();
            int w = tid >> 5, lane = tid & 31;
            const float4* qv4 = (const float4*)sm;
            const float4* vv4 = (const float4*)(sm + H_);
            for (int i = 0; i < 8; i++) {
                int n = c * 128 + w * 8 + i;
                const float4* kp = (const float4*)&g_keys[(size_t)(b * N_ + n) * H_];
                float acc = 0.f;
#pragma unroll
                for (int v8 = 0; v8 < 8; v8++) {
                    float4 kv = kp[lane + 32 * v8];
                    float4 q4 = qv4[lane + 32 * v8];
                    float4 vv = vv4[lane + 32 * v8];
                    acc += vv.x * tanh_fast(q4.x + kv.x);
                    acc += vv.y * tanh_fast(q4.y + kv.y);
                    acc += vv.z * tanh_fast(q4.z + kv.z);
                    acc += vv.w * tanh_fast(q4.w + kv.w);
                }
#pragma unroll
                for (int o = 16; o; o >>= 1) acc += __shfl_xor_sync(0xffffffffu, acc, o);
                if (lane == 0) {
                    float mk = vmask[b * N_ + n];
                    g_score[b * N_ + n] = (mk > 0.f) ? acc : -1e9f;
                }
            }
        }
        gbar(target, 2);

        // ---- P5: softmax (one b per CTA, 512 threads = N cols) ----
        if (bid < B_) {
            int b = bid;
            int w = tid >> 5, lane = tid & 31;
            float s = g_score[b * N_ + tid];
            float m = s;
#pragma unroll
            for (int o = 16; o; o >>= 1) m = fmaxf(m, __shfl_xor_sync(0xffffffffu, m, o));
            if (lane == 0) red[w] = m;
            __syncthreads();
            float M = red[0];
#pragma unroll
            for (int i = 1; i < 16; i++) M = fmaxf(M, red[i]);
            float p = expf(s - M);
            float ss = p;
#pragma unroll
            for (int o = 16; o; o >>= 1) ss += __shfl_xor_sync(0xffffffffu, ss, o);
            if (lane == 0) red[16 + w] = ss;
            __syncthreads();
            float Z = red[16];
#pragma unroll
            for (int i = 1; i < 16; i++) Z += red[16 + i];
            float a = p / Z;
            g_attn[b * N_ + tid] = a;
            attn_out[((size_t)b * L_ + t) * N_ + tid] = a;
        }
        gbar(target, -1);

        // ---- P6: context (128 units of (b, 512-h chunk)), static ----
        if (bid < 128) {
            int b = bid >> 1, hb = bid & 1;
            sm[tid] = g_attn[b * N_ + tid];
            __syncthreads();
            int h = hb * 512 + tid;
            const float* vp = &value[(size_t)b * N_ * H_ + h];
            float acc = 0.f;
#pragma unroll 8
            for (int n = 0; n < N_; n++) acc += sm[n] * vp[(size_t)n * H_];
            g_xf[b * 2 * H_ + H_ + h] = acc;
        }
        gbar(target, -1);

        // ---- P7: final ctx-half (128 units, Kc=64, s = 8..23), static ----
        if (bid < 128) {
            int nt = bid & 7, s16 = bid >> 3;
            int k0 = H_ + s16 * 64;
            gemm_tile(g_xf + k0, 2 * H_,
                      Wm + (size_t)nt * 128 * 2 * H_ + k0, 2 * H_,
                      g_fp + (size_t)(8 + s16) * B_ * H_ + nt * 128, H_, 64, sm);
        }
        gbar(target, -1);

        // ---- P8: final elementwise + stage next emb ----
        {
            int i = bid * NTHR + tid;
            if (i < B_ * H_) {
                int b = i >> 10, j = i & 1023;
                float a = bm[j];
#pragma unroll
                for (int s = 0; s < SF; s++) a += g_fp[((size_t)s * B_ + b) * H_ + j];
                float y = tanhf(a);
                out[((size_t)b * L_ + t) * H_ + j] = y;
                g_h[i] = y;
                g_xg1[b * KA + E_ + j] = y;
            }
            if (t + 1 < L_ && i < B_ * E_) {
                int b = i >> 9, e = i & 511;
                g_xg1[b * KA + e] = emb[((size_t)b * L_ + t + 1) * E_ + e];
            }
        }
        gbar(target, -1);
    }
}

// ---------------- launch: ONE graph node ----------------
extern "C" void kernel_launch(void* const* d_in, const int* in_sizes, int n_in,
                              void* d_out, int out_size) {
    const float* emb    = (const float*)d_in[0];
    const float* value  = (const float*)d_in[1];
    const float* vmask  = (const float*)d_in[2];
    const float* state  = (const float*)d_in[3];
    const float* W_ih   = (const float*)d_in[4];
    const float* b_ih   = (const float*)d_in[5];
    const float* W_hh   = (const float*)d_in[6];
    const float* b_hh   = (const float*)d_in[7];
    const float* Wq     = (const float*)d_in[8];
    const float* Wk     = (const float*)d_in[9];
    const float* v_att  = (const float*)d_in[10];
    const float* Wm     = (const float*)d_in[11];
    const float* bm     = (const float*)d_in[12];

    float* out      = (float*)d_out;                 // outputs: B x L x H
    float* attn_out = out + (size_t)B_ * L_ * H_;    // attns:   B x L x N

    decoder_all<<<NBLK, NTHR>>>(emb, value, vmask, state, W_ih, b_ih, W_hh, b_hh,
                                Wq, Wk, v_att, Wm, bm, out, attn_out);
}

// round 5
// speedup vs baseline: 1.6353x; 1.0003x over previous
#include <cuda_runtime.h>
#include <cuda_bf16.h>
#include <math.h>

#define B_ 64
#define L_ 128
#define E_ 512
#define N_ 512
#define H_ 1024
#define G3 3072
#define KA 1536
#define NBLK 148
#define NTHR 512

#define S1 16      /* splits for gx-h and gh (Kc=64) */
#define SQ 16      /* q splits (Kc=64) */
#define SFTOT 32   /* final splits: 16 rnn-half (P3) + 16 ctx-half (P7), Kc=64 */

// ---------------- device scratch (static, no allocations) ----------------
__device__ __nv_bfloat16 g_keysb[(size_t)B_ * N_ * H_];  // 67 MB
__device__ __nv_bfloat16 g_valb[(size_t)B_ * N_ * H_];   // 67 MB
__device__ float g_gxe[(size_t)B_ * L_ * G3];            // 100 MB: emb @ W_ih_emb^T
__device__ float g_h[B_ * H_];
__device__ float g_xf[B_ * 2 * H_];                      // [rnn | ctx]
__device__ float g_score[B_ * N_];
__device__ float g_attn[B_ * N_];
__device__ float g_gxp[(size_t)S1 * B_ * G3];
__device__ float g_ghp[(size_t)S1 * B_ * G3];
__device__ float g_qp[(size_t)SQ * B_ * H_];
__device__ float g_fp[(size_t)SFTOT * B_ * H_];
__device__ unsigned g_cnt;
__device__ unsigned g_gen;
__device__ unsigned g_q[4];

__device__ __forceinline__ float tanh_fast(float x) {
    float y;
    asm("tanh.approx.f32 %0, %1;" : "=f"(y) : "f"(x));
    return y;
}

// ---------------- grid barrier; winner optionally resets a queue ----------------
__device__ __forceinline__ void gbar(unsigned& target, int resetq) {
    __syncthreads();
    if (threadIdx.x == 0) {
        __threadfence();
        if (atomicAdd(&g_cnt, 1u) == (unsigned)NBLK - 1u) {
            atomicExch(&g_cnt, 0u);
            if (resetq >= 0) atomicExch(&g_q[resetq], 0u);
            __threadfence();
            atomicAdd(&g_gen, 1u);
        } else {
            while ((int)(*(volatile unsigned*)&g_gen - target) < 0) __nanosleep(32);
        }
        target++;
    }
    __syncthreads();
}

__device__ __forceinline__ int qfetch(int c, int* s_u) {
    __syncthreads();
    if (threadIdx.x == 0) *s_u = (int)atomicAdd(&g_q[c], 1u);
    __syncthreads();
    return *s_u;
}

// ---------------- 64(M) x 256(N) x Kc SGEMM tile, double-buffered, FFMA-bound ----
// C[m][n] = sum_{k<Kc} Ap[m*lda+k] * Wp[n*ldw+k]
// thread (tx=tid&31, ty=tid>>5): rows ty*4..+3, cols tx*4..+3 and 128+tx*4..+3
__device__ __forceinline__ void gemm_tile(
    const float* __restrict__ Ap, int lda,
    const float* __restrict__ Wp, int ldw,
    void* Co, int ldc, int Kc, int bf16out, float* sm)
{
    const int tid = threadIdx.x;
    const int am = tid >> 3, ak = (tid & 7) << 1;   // A stage: 64x16 via float2
    const int wn = tid >> 1, wk = (tid & 1) << 3;   // W stage: 256x16 via 2x float4
    const int tx = tid & 31, ty = tid >> 5;
    const int nkt = Kc >> 4;

    float acc[4][8] = {};
    float2 areg  = *(const float2*)(Ap + (size_t)am * lda + ak);
    float4 wreg0 = *(const float4*)(Wp + (size_t)wn * ldw + wk);
    float4 wreg1 = *(const float4*)(Wp + (size_t)wn * ldw + wk + 4);

    __syncthreads();   // protect smem from previous use
    for (int kt = 0; kt < nkt; kt++) {
        float* As = sm + (kt & 1) * 5248;
        float* Ws = As + 1088;
        As[(ak + 0) * 68 + am] = areg.x;
        As[(ak + 1) * 68 + am] = areg.y;
        Ws[(wk + 0) * 260 + wn] = wreg0.x;
        Ws[(wk + 1) * 260 + wn] = wreg0.y;
        Ws[(wk + 2) * 260 + wn] = wreg0.z;
        Ws[(wk + 3) * 260 + wn] = wreg0.w;
        Ws[(wk + 4) * 260 + wn] = wreg1.x;
        Ws[(wk + 5) * 260 + wn] = wreg1.y;
        Ws[(wk + 6) * 260 + wn] = wreg1.z;
        Ws[(wk + 7) * 260 + wn] = wreg1.w;
        if (kt + 1 < nkt) {
            const float* Ap2 = Ap + (kt + 1) * 16;
            const float* Wp2 = Wp + (kt + 1) * 16;
            areg  = *(const float2*)(Ap2 + (size_t)am * lda + ak);
            wreg0 = *(const float4*)(Wp2 + (size_t)wn * ldw + wk);
            wreg1 = *(const float4*)(Wp2 + (size_t)wn * ldw + wk + 4);
        }
        __syncthreads();
#pragma unroll
        for (int kk = 0; kk < 16; kk++) {
            float4 a  = *(const float4*)(As + kk * 68 + (ty << 2));
            float4 w0 = *(const float4*)(Ws + kk * 260 + (tx << 2));
            float4 w1 = *(const float4*)(Ws + kk * 260 + 128 + (tx << 2));
            acc[0][0] += a.x * w0.x; acc[0][1] += a.x * w0.y; acc[0][2] += a.x * w0.z; acc[0][3] += a.x * w0.w;
            acc[1][0] += a.y * w0.x; acc[1][1] += a.y * w0.y; acc[1][2] += a.y * w0.z; acc[1][3] += a.y * w0.w;
            acc[2][0] += a.z * w0.x; acc[2][1] += a.z * w0.y; acc[2][2] += a.z * w0.z; acc[2][3] += a.z * w0.w;
            acc[3][0] += a.w * w0.x; acc[3][1] += a.w * w0.y; acc[3][2] += a.w * w0.z; acc[3][3] += a.w * w0.w;
            acc[0][4] += a.x * w1.x; acc[0][5] += a.x * w1.y; acc[0][6] += a.x * w1.z; acc[0][7] += a.x * w1.w;
            acc[1][4] += a.y * w1.x; acc[1][5] += a.y * w1.y; acc[1][6] += a.y * w1.z; acc[1][7] += a.y * w1.w;
            acc[2][4] += a.z * w1.x; acc[2][5] += a.z * w1.y; acc[2][6] += a.z * w1.z; acc[2][7] += a.z * w1.w;
            acc[3][4] += a.w * w1.x; acc[3][5] += a.w * w1.y; acc[3][6] += a.w * w1.z; acc[3][7] += a.w * w1.w;
        }
    }
    if (!bf16out) {
        float* C = (float*)Co;
#pragma unroll
        for (int i = 0; i < 4; i++) {
            int row = (ty << 2) + i;
            *(float4*)(C + (size_t)row * ldc + (tx << 2)) =
                make_float4(acc[i][0], acc[i][1], acc[i][2], acc[i][3]);
            *(float4*)(C + (size_t)row * ldc + 128 + (tx << 2)) =
                make_float4(acc[i][4], acc[i][5], acc[i][6], acc[i][7]);
        }
    } else {
        __nv_bfloat16* C = (__nv_bfloat16*)Co;
#pragma unroll
        for (int i = 0; i < 4; i++) {
            int row = (ty << 2) + i;
            __nv_bfloat162* p0 = (__nv_bfloat162*)(C + (size_t)row * ldc + (tx << 2));
            p0[0] = __floats2bfloat162_rn(acc[i][0], acc[i][1]);
            p0[1] = __floats2bfloat162_rn(acc[i][2], acc[i][3]);
            __nv_bfloat162* p1 = (__nv_bfloat162*)(C + (size_t)row * ldc + 128 + (tx << 2));
            p1[0] = __floats2bfloat162_rn(acc[i][4], acc[i][5]);
            p1[1] = __floats2bfloat162_rn(acc[i][6], acc[i][7]);
        }
    }
}

// ---------------- the one persistent kernel ----------------
__global__ __launch_bounds__(NTHR, 1) void decoder_all(
    const float* __restrict__ emb,   const float* __restrict__ value,
    const float* __restrict__ vmask, const float* __restrict__ state,
    const float* __restrict__ W_ih,  const float* __restrict__ b_ih,
    const float* __restrict__ W_hh,  const float* __restrict__ b_hh,
    const float* __restrict__ Wq,    const float* __restrict__ Wk,
    const float* __restrict__ v_att, const float* __restrict__ Wm,
    const float* __restrict__ bm,
    float* __restrict__ out, float* __restrict__ attn_out)
{
    __shared__ float sm[10496];   // 2 x (16x68 + 16x260) floats = 42 KB; reused by score/ctx
    __shared__ float red[32];
    __shared__ int   s_u;
    const int bid = blockIdx.x, tid = threadIdx.x;
    unsigned target = 0;
    if (tid == 0) target = *(volatile unsigned*)&g_gen + 1u;
    __syncthreads();

    // ================= phase 0 =================
    // init h; bf16 copy of value; keys GEMM (bf16 out); emb-part of gx for all t
    {
        int i = bid * NTHR + tid;
        if (i < B_ * H_) g_h[i] = state[i];
    }
    {
        const float2* vf = (const float2*)value;
        __nv_bfloat162* vb = (__nv_bfloat162*)g_valb;
        int np = B_ * N_ * H_ / 2;
        for (int i = bid * NTHR + tid; i < np; i += NBLK * NTHR) {
            float2 f = vf[i];
            vb[i] = __floats2bfloat162_rn(f.x, f.y);
        }
    }
    for (;;) {
        int u = qfetch(0, &s_u);
        if (u >= 2048 + 1536) break;
        if (u < 2048) {
            // keys[b*n, :] = value row @ Wk^T : M=32768, Nn=1024, K=1024
            int mt = u >> 2, nt = u & 3;
            gemm_tile(value + (size_t)mt * 64 * H_, H_,
                      Wk + (size_t)nt * 256 * H_, H_,
                      g_keysb + (size_t)mt * 64 * H_ + nt * 256, H_, H_, 1, sm);
        } else {
            // gxe[b*L+t, :] = emb row @ W_ih[:, :E]^T : M=8192, Nn=3072, K=512
            int u2 = u - 2048;
            int mt = u2 / 12, nt = u2 % 12;
            gemm_tile(emb + (size_t)mt * 64 * E_, E_,
                      W_ih + (size_t)nt * 256 * KA, KA,
                      g_gxe + (size_t)mt * 64 * G3 + nt * 256, G3, E_, 0, sm);
        }
    }
    gbar(target, 0);

    for (int t = 0; t < L_; t++) {
        // ---- P1: gx-hpart (192 units) + gh (192 units), Kc=64, queue 1 ----
        for (;;) {
            int u = qfetch(1, &s_u);
            if (u >= 384) break;
            if (u < 192) {
                int nt = u % 12, s = u / 12;
                gemm_tile(g_h + s * 64, H_,
                          W_ih + (size_t)nt * 256 * KA + E_ + s * 64, KA,
                          g_gxp + (size_t)s * B_ * G3 + nt * 256, G3, 64, 0, sm);
            } else {
                int u2 = u - 192;
                int nt = u2 % 12, s = u2 / 12;
                gemm_tile(g_h + s * 64, H_,
                          W_hh + (size_t)nt * 256 * H_ + s * 64, H_,
                          g_ghp + (size_t)s * B_ * G3 + nt * 256, G3, 64, 0, sm);
            }
        }
        gbar(target, 1);

        // ---- P2: GRU elementwise (gxe + partial sums + gates) ----
        {
            int i = bid * NTHR + tid;
            if (i < B_ * H_) {
                int b = i >> 10, j = i & 1023;
                const float* ge = &g_gxe[(size_t)(b * L_ + t) * G3];
                float gxr = ge[j], gxz = ge[H_ + j], gxn = ge[2 * H_ + j];
                float ghr = 0.f, ghz = 0.f, ghn = 0.f;
#pragma unroll
                for (int s = 0; s < S1; s++) {
                    const float* p = &g_gxp[((size_t)s * B_ + b) * G3];
                    gxr += p[j]; gxz += p[H_ + j]; gxn += p[2 * H_ + j];
                }
#pragma unroll
                for (int s = 0; s < S1; s++) {
                    const float* p = &g_ghp[((size_t)s * B_ + b) * G3];
                    ghr += p[j]; ghz += p[H_ + j]; ghn += p[2 * H_ + j];
                }
                float r = 1.f / (1.f + expf(-(gxr + b_ih[j]        + ghr + b_hh[j])));
                float z = 1.f / (1.f + expf(-(gxz + b_ih[H_ + j]   + ghz + b_hh[H_ + j])));
                float n = tanhf(gxn + b_ih[2 * H_ + j] + r * (ghn + b_hh[2 * H_ + j]));
                float h = g_h[i];
                g_xf[b * 2 * H_ + j] = (1.f - z) * n + z * h;
            }
        }
        gbar(target, -1);

        // ---- P3: q GEMM (64 units) + final rnn-half (64 units), Kc=64, static ----
        if (bid < 128) {
            if (bid < 64) {
                int nt = bid & 3, s = bid >> 2;
                gemm_tile(g_xf + s * 64, 2 * H_,
                          Wq + (size_t)nt * 256 * H_ + s * 64, H_,
                          g_qp + (size_t)s * B_ * H_ + nt * 256, H_, 64, 0, sm);
            } else {
                int u2 = bid - 64;
                int nt = u2 & 3, s = u2 >> 2;
                gemm_tile(g_xf + s * 64, 2 * H_,
                          Wm + (size_t)nt * 256 * 2 * H_ + s * 64, 2 * H_,
                          g_fp + (size_t)s * B_ * H_ + nt * 256, H_, 64, 0, sm);
            }
        }
        gbar(target, -1);

        // ---- P4: score (256 units of (b, 128-n chunk)), bf16 keys, queue 2 ----
        for (;;) {
            int u = qfetch(2, &s_u);
            if (u >= B_ * 4) break;
            int b = u >> 2, c = u & 3;
            for (int j = tid; j < H_; j += NTHR) {
                float a = 0.f;
#pragma unroll
                for (int s = 0; s < SQ; s++) a += g_qp[((size_t)s * B_ + b) * H_ + j];
                sm[j] = a;
                sm[H_ + j] = v_att[j];
            }
            __syncthreads();
            int w = tid >> 5, lane = tid & 31;
            for (int i = 0; i < 8; i++) {
                int n = c * 128 + w * 8 + i;
                const uint4* kp = (const uint4*)(g_keysb + (size_t)(b * N_ + n) * H_);
                float acc = 0.f;
#pragma unroll
                for (int j2 = 0; j2 < 4; j2++) {
                    uint4 kv = kp[lane + 32 * j2];
                    int c8 = (lane + 32 * j2) << 3;
                    float4 q0 = *(const float4*)(sm + c8);
                    float4 q1 = *(const float4*)(sm + c8 + 4);
                    float4 v0 = *(const float4*)(sm + H_ + c8);
                    float4 v1 = *(const float4*)(sm + H_ + c8 + 4);
                    acc += v0.x * tanh_fast(q0.x + __uint_as_float(kv.x << 16));
                    acc += v0.y * tanh_fast(q0.y + __uint_as_float(kv.x & 0xFFFF0000u));
                    acc += v0.z * tanh_fast(q0.z + __uint_as_float(kv.y << 16));
                    acc += v0.w * tanh_fast(q0.w + __uint_as_float(kv.y & 0xFFFF0000u));
                    acc += v1.x * tanh_fast(q1.x + __uint_as_float(kv.z << 16));
                    acc += v1.y * tanh_fast(q1.y + __uint_as_float(kv.z & 0xFFFF0000u));
                    acc += v1.z * tanh_fast(q1.z + __uint_as_float(kv.w << 16));
                    acc += v1.w * tanh_fast(q1.w + __uint_as_float(kv.w & 0xFFFF0000u));
                }
#pragma unroll
                for (int o = 16; o; o >>= 1) acc += __shfl_xor_sync(0xffffffffu, acc, o);
                if (lane == 0) {
                    float mk = vmask[b * N_ + n];
                    g_score[b * N_ + n] = (mk > 0.f) ? acc : -1e9f;
                }
            }
        }
        gbar(target, 2);

        // ---- P5: softmax (one b per CTA) ----
        if (bid < B_) {
            int b = bid;
            int w = tid >> 5, lane = tid & 31;
            float s = g_score[b * N_ + tid];
            float m = s;
#pragma unroll
            for (int o = 16; o; o >>= 1) m = fmaxf(m, __shfl_xor_sync(0xffffffffu, m, o));
            if (lane == 0) red[w] = m;
            __syncthreads();
            float M = red[0];
#pragma unroll
            for (int i = 1; i < 16; i++) M = fmaxf(M, red[i]);
            float p = expf(s - M);
            float ss = p;
#pragma unroll
            for (int o = 16; o; o >>= 1) ss += __shfl_xor_sync(0xffffffffu, ss, o);
            if (lane == 0) red[16 + w] = ss;
            __syncthreads();
            float Z = red[16];
#pragma unroll
            for (int i = 1; i < 16; i++) Z += red[16 + i];
            float a = p / Z;
            g_attn[b * N_ + tid] = a;
            attn_out[((size_t)b * L_ + t) * N_ + tid] = a;
        }
        gbar(target, -1);

        // ---- P6: context from bf16 value (one b per CTA, thread = bf162 h-pair) ----
        if (bid < B_) {
            int b = bid;
            sm[tid] = g_attn[b * N_ + tid];
            __syncthreads();
            const __nv_bfloat162* vp = (const __nv_bfloat162*)(g_valb + (size_t)b * N_ * H_) + tid;
            float a0 = 0.f, a1 = 0.f;
#pragma unroll 8
            for (int n = 0; n < N_; n++) {
                float2 f = __bfloat1622float2(vp[(size_t)n * (H_ / 2)]);
                float wv = sm[n];
                a0 += wv * f.x;
                a1 += wv * f.y;
            }
            g_xf[b * 2 * H_ + H_ + 2 * tid]     = a0;
            g_xf[b * 2 * H_ + H_ + 2 * tid + 1] = a1;
        }
        gbar(target, -1);

        // ---- P7: final ctx-half (64 units, Kc=64), static ----
        if (bid < 64) {
            int nt = bid & 3, s16 = bid >> 2;
            int k0 = H_ + s16 * 64;
            gemm_tile(g_xf + k0, 2 * H_,
                      Wm + (size_t)nt * 256 * 2 * H_ + k0, 2 * H_,
                      g_fp + (size_t)(16 + s16) * B_ * H_ + nt * 256, H_, 64, 0, sm);
        }
        gbar(target, -1);

        // ---- P8: final elementwise ----
        {
            int i = bid * NTHR + tid;
            if (i < B_ * H_) {
                int b = i >> 10, j = i & 1023;
                float a = bm[j];
#pragma unroll
                for (int s = 0; s < SFTOT; s++) a += g_fp[((size_t)s * B_ + b) * H_ + j];
                float y = tanhf(a);
                out[((size_t)b * L_ + t) * H_ + j] = y;
                g_h[i] = y;
            }
        }
        gbar(target, -1);
    }
}

// ---------------- launch: ONE graph node ----------------
extern "C" void kernel_launch(void* const* d_in, const int* in_sizes, int n_in,
                              void* d_out, int out_size) {
    const float* emb    = (const float*)d_in[0];
    const float* value  = (const float*)d_in[1];
    const float* vmask  = (const float*)d_in[2];
    const float* state  = (const float*)d_in[3];
    const float* W_ih   = (const float*)d_in[4];
    const float* b_ih   = (const float*)d_in[5];
    const float* W_hh   = (const float*)d_in[6];
    const float* b_hh   = (const float*)d_in[7];
    const float* Wq     = (const float*)d_in[8];
    const float* Wk     = (const float*)d_in[9];
    const float* v_att  = (const float*)d_in[10];
    const float* Wm     = (const float*)d_in[11];
    const float* bm     = (const float*)d_in[12];

    float* out      = (float*)d_out;                 // outputs: B x L x H
    float* attn_out = out + (size_t)B_ * L_ * H_;    // attns:   B x L x N

    decoder_all<<<NBLK, NTHR>>>(emb, value, vmask, state, W_ih, b_ih, W_hh, b_hh,
                                Wq, Wk, v_att, Wm, bm, out, attn_out);
}

// round 6
// speedup vs baseline: 1.6850x; 1.0304x over previous
#include <cuda_runtime.h>
#include <cuda_bf16.h>
#include <math.h>

#define B_ 64
#define L_ 128
#define E_ 512
#define N_ 512
#define H_ 1024
#define G3 3072
#define KA 1536
#define NBLK 148
#define NTHR 512

#define S1 16      /* splits for gx-h and gh (Kc=64) */
#define SQ 16      /* q splits (Kc=64) */
#define SFTOT 32   /* final splits: 16 rnn-half (P3) + 16 ctx-half (P7), Kc=64 */

// ---------------- device scratch (static, no allocations) ----------------
__device__ __nv_bfloat16 g_keysb[(size_t)B_ * N_ * H_];  // 67 MB
__device__ __nv_bfloat16 g_valb[(size_t)B_ * N_ * H_];   // 67 MB
__device__ float g_gxe[(size_t)B_ * L_ * G3];            // 100 MB: emb @ W_ih_emb^T
__device__ float g_h[B_ * H_];
__device__ float g_xf[B_ * 2 * H_];                      // [rnn | ctx]
__device__ float g_score[B_ * N_];
__device__ float g_attn[B_ * N_];
__device__ float g_gxp[(size_t)S1 * B_ * G3];
__device__ float g_ghp[(size_t)S1 * B_ * G3];
__device__ float g_qp[(size_t)SQ * B_ * H_];
__device__ float g_fp[(size_t)SFTOT * B_ * H_];
__device__ unsigned g_cnt;
__device__ unsigned g_gen;
__device__ unsigned g_q[4];

__device__ __forceinline__ float tanh_fast(float x) {
    float y;
    asm("tanh.approx.f32 %0, %1;" : "=f"(y) : "f"(x));
    return y;
}

// ---------------- grid barrier; winner optionally resets a queue ----------------
__device__ __forceinline__ void gbar(unsigned& target, int resetq) {
    __syncthreads();
    if (threadIdx.x == 0) {
        __threadfence();
        if (atomicAdd(&g_cnt, 1u) == (unsigned)NBLK - 1u) {
            atomicExch(&g_cnt, 0u);
            if (resetq >= 0) atomicExch(&g_q[resetq], 0u);
            __threadfence();
            atomicAdd(&g_gen, 1u);
        } else {
            while ((int)(*(volatile unsigned*)&g_gen - target) < 0) __nanosleep(32);
        }
        target++;
    }
    __syncthreads();
}

__device__ __forceinline__ int qfetch(int c, int* s_u) {
    __syncthreads();
    if (threadIdx.x == 0) *s_u = (int)atomicAdd(&g_q[c], 1u);
    __syncthreads();
    return *s_u;
}

// ---------------- 64(M) x 256(N) x Kc SGEMM tile, double-buffered, FFMA-bound ----
// C[m][n] = sum_{k<Kc} Ap[m*lda+k] * Wp[n*ldw+k]
// thread (tx=tid&31, ty=tid>>5): rows ty*4..+3, cols tx*4..+3 and 128+tx*4..+3
__device__ __forceinline__ void gemm_tile(
    const float* __restrict__ Ap, int lda,
    const float* __restrict__ Wp, int ldw,
    void* Co, int ldc, int Kc, int bf16out, float* sm)
{
    const int tid = threadIdx.x;
    const int am = tid >> 3, ak = (tid & 7) << 1;   // A stage: 64x16 via float2
    const int wn = tid >> 1, wk = (tid & 1) << 3;   // W stage: 256x16 via 2x float4
    const int tx = tid & 31, ty = tid >> 5;
    const int nkt = Kc >> 4;

    float acc[4][8] = {};
    float2 areg  = *(const float2*)(Ap + (size_t)am * lda + ak);
    float4 wreg0 = *(const float4*)(Wp + (size_t)wn * ldw + wk);
    float4 wreg1 = *(const float4*)(Wp + (size_t)wn * ldw + wk + 4);

    __syncthreads();   // protect smem from previous use
    for (int kt = 0; kt < nkt; kt++) {
        float* As = sm + (kt & 1) * 5248;
        float* Ws = As + 1088;
        As[(ak + 0) * 68 + am] = areg.x;
        As[(ak + 1) * 68 + am] = areg.y;
        Ws[(wk + 0) * 260 + wn] = wreg0.x;
        Ws[(wk + 1) * 260 + wn] = wreg0.y;
        Ws[(wk + 2) * 260 + wn] = wreg0.z;
        Ws[(wk + 3) * 260 + wn] = wreg0.w;
        Ws[(wk + 4) * 260 + wn] = wreg1.x;
        Ws[(wk + 5) * 260 + wn] = wreg1.y;
        Ws[(wk + 6) * 260 + wn] = wreg1.z;
        Ws[(wk + 7) * 260 + wn] = wreg1.w;
        if (kt + 1 < nkt) {
            const float* Ap2 = Ap + (kt + 1) * 16;
            const float* Wp2 = Wp + (kt + 1) * 16;
            areg  = *(const float2*)(Ap2 + (size_t)am * lda + ak);
            wreg0 = *(const float4*)(Wp2 + (size_t)wn * ldw + wk);
            wreg1 = *(const float4*)(Wp2 + (size_t)wn * ldw + wk + 4);
        }
        __syncthreads();
#pragma unroll
        for (int kk = 0; kk < 16; kk++) {
            float4 a  = *(const float4*)(As + kk * 68 + (ty << 2));
            float4 w0 = *(const float4*)(Ws + kk * 260 + (tx << 2));
            float4 w1 = *(const float4*)(Ws + kk * 260 + 128 + (tx << 2));
            acc[0][0] += a.x * w0.x; acc[0][1] += a.x * w0.y; acc[0][2] += a.x * w0.z; acc[0][3] += a.x * w0.w;
            acc[1][0] += a.y * w0.x; acc[1][1] += a.y * w0.y; acc[1][2] += a.y * w0.z; acc[1][3] += a.y * w0.w;
            acc[2][0] += a.z * w0.x; acc[2][1] += a.z * w0.y; acc[2][2] += a.z * w0.z; acc[2][3] += a.z * w0.w;
            acc[3][0] += a.w * w0.x; acc[3][1] += a.w * w0.y; acc[3][2] += a.w * w0.z; acc[3][3] += a.w * w0.w;
            acc[0][4] += a.x * w1.x; acc[0][5] += a.x * w1.y; acc[0][6] += a.x * w1.z; acc[0][7] += a.x * w1.w;
            acc[1][4] += a.y * w1.x; acc[1][5] += a.y * w1.y; acc[1][6] += a.y * w1.z; acc[1][7] += a.y * w1.w;
            acc[2][4] += a.z * w1.x; acc[2][5] += a.z * w1.y; acc[2][6] += a.z * w1.z; acc[2][7] += a.z * w1.w;
            acc[3][4] += a.w * w1.x; acc[3][5] += a.w * w1.y; acc[3][6] += a.w * w1.z; acc[3][7] += a.w * w1.w;
        }
    }
    if (!bf16out) {
        float* C = (float*)Co;
#pragma unroll
        for (int i = 0; i < 4; i++) {
            int row = (ty << 2) + i;
            *(float4*)(C + (size_t)row * ldc + (tx << 2)) =
                make_float4(acc[i][0], acc[i][1], acc[i][2], acc[i][3]);
            *(float4*)(C + (size_t)row * ldc + 128 + (tx << 2)) =
                make_float4(acc[i][4], acc[i][5], acc[i][6], acc[i][7]);
        }
    } else {
        __nv_bfloat16* C = (__nv_bfloat16*)Co;
#pragma unroll
        for (int i = 0; i < 4; i++) {
            int row = (ty << 2) + i;
            __nv_bfloat162* p0 = (__nv_bfloat162*)(C + (size_t)row * ldc + (tx << 2));
            p0[0] = __floats2bfloat162_rn(acc[i][0], acc[i][1]);
            p0[1] = __floats2bfloat162_rn(acc[i][2], acc[i][3]);
            __nv_bfloat162* p1 = (__nv_bfloat162*)(C + (size_t)row * ldc + 128 + (tx << 2));
            p1[0] = __floats2bfloat162_rn(acc[i][4], acc[i][5]);
            p1[1] = __floats2bfloat162_rn(acc[i][6], acc[i][7]);
        }
    }
}

// ---------------- the one persistent kernel ----------------
__global__ __launch_bounds__(NTHR, 1) void decoder_all(
    const float* __restrict__ emb,   const float* __restrict__ value,
    const float* __restrict__ vmask, const float* __restrict__ state,
    const float* __restrict__ W_ih,  const float* __restrict__ b_ih,
    const float* __restrict__ W_hh,  const float* __restrict__ b_hh,
    const float* __restrict__ Wq,    const float* __restrict__ Wk,
    const float* __restrict__ v_att, const float* __restrict__ Wm,
    const float* __restrict__ bm,
    float* __restrict__ out, float* __restrict__ attn_out)
{
    __shared__ float sm[10496];   // 2 x (16x68 + 16x260) floats = 42 KB; reused by score/ctx
    __shared__ float red[32];
    __shared__ int   s_u;
    const int bid = blockIdx.x, tid = threadIdx.x;
    unsigned target = 0;
    if (tid == 0) target = *(volatile unsigned*)&g_gen + 1u;
    __syncthreads();

    // ================= phase 0 =================
    // init h; bf16 copy of value; keys GEMM (bf16 out); emb-part of gx for all t
    {
        int i = bid * NTHR + tid;
        if (i < B_ * H_) g_h[i] = state[i];
    }
    {
        const float2* vf = (const float2*)value;
        __nv_bfloat162* vb = (__nv_bfloat162*)g_valb;
        int np = B_ * N_ * H_ / 2;
        for (int i = bid * NTHR + tid; i < np; i += NBLK * NTHR) {
            float2 f = vf[i];
            vb[i] = __floats2bfloat162_rn(f.x, f.y);
        }
    }
    for (;;) {
        int u = qfetch(0, &s_u);
        if (u >= 2048 + 1536) break;
        if (u < 2048) {
            // keys[b*n, :] = value row @ Wk^T : M=32768, Nn=1024, K=1024
            int mt = u >> 2, nt = u & 3;
            gemm_tile(value + (size_t)mt * 64 * H_, H_,
                      Wk + (size_t)nt * 256 * H_, H_,
                      g_keysb + (size_t)mt * 64 * H_ + nt * 256, H_, H_, 1, sm);
        } else {
            // gxe[b*L+t, :] = emb row @ W_ih[:, :E]^T : M=8192, Nn=3072, K=512
            int u2 = u - 2048;
            int mt = u2 / 12, nt = u2 % 12;
            gemm_tile(emb + (size_t)mt * 64 * E_, E_,
                      W_ih + (size_t)nt * 256 * KA, KA,
                      g_gxe + (size_t)mt * 64 * G3 + nt * 256, G3, E_, 0, sm);
        }
    }
    gbar(target, 0);

    for (int t = 0; t < L_; t++) {
        // ---- P1: gx-hpart (192 units) + gh (192 units), Kc=64, queue 1 ----
        for (;;) {
            int u = qfetch(1, &s_u);
            if (u >= 384) break;
            if (u < 192) {
                int nt = u % 12, s = u / 12;
                gemm_tile(g_h + s * 64, H_,
                          W_ih + (size_t)nt * 256 * KA + E_ + s * 64, KA,
                          g_gxp + (size_t)s * B_ * G3 + nt * 256, G3, 64, 0, sm);
            } else {
                int u2 = u - 192;
                int nt = u2 % 12, s = u2 / 12;
                gemm_tile(g_h + s * 64, H_,
                          W_hh + (size_t)nt * 256 * H_ + s * 64, H_,
                          g_ghp + (size_t)s * B_ * G3 + nt * 256, G3, 64, 0, sm);
            }
        }
        gbar(target, 1);

        // ---- P2: GRU elementwise (gxe + partial sums + gates) ----
        {
            int i = bid * NTHR + tid;
            if (i < B_ * H_) {
                int b = i >> 10, j = i & 1023;
                const float* ge = &g_gxe[(size_t)(b * L_ + t) * G3];
                float gxr = ge[j], gxz = ge[H_ + j], gxn = ge[2 * H_ + j];
                float ghr = 0.f, ghz = 0.f, ghn = 0.f;
#pragma unroll
                for (int s = 0; s < S1; s++) {
                    const float* p = &g_gxp[((size_t)s * B_ + b) * G3];
                    gxr += p[j]; gxz += p[H_ + j]; gxn += p[2 * H_ + j];
                }
#pragma unroll
                for (int s = 0; s < S1; s++) {
                    const float* p = &g_ghp[((size_t)s * B_ + b) * G3];
                    ghr += p[j]; ghz += p[H_ + j]; ghn += p[2 * H_ + j];
                }
                float r = 1.f / (1.f + expf(-(gxr + b_ih[j]        + ghr + b_hh[j])));
                float z = 1.f / (1.f + expf(-(gxz + b_ih[H_ + j]   + ghz + b_hh[H_ + j])));
                float n = tanhf(gxn + b_ih[2 * H_ + j] + r * (ghn + b_hh[2 * H_ + j]));
                float h = g_h[i];
                g_xf[b * 2 * H_ + j] = (1.f - z) * n + z * h;
            }
        }
        gbar(target, -1);

        // ---- P3: q GEMM (64 units) + final rnn-half (64 units), Kc=64, static ----
        if (bid < 128) {
            if (bid < 64) {
                int nt = bid & 3, s = bid >> 2;
                gemm_tile(g_xf + s * 64, 2 * H_,
                          Wq + (size_t)nt * 256 * H_ + s * 64, H_,
                          g_qp + (size_t)s * B_ * H_ + nt * 256, H_, 64, 0, sm);
            } else {
                int u2 = bid - 64;
                int nt = u2 & 3, s = u2 >> 2;
                gemm_tile(g_xf + s * 64, 2 * H_,
                          Wm + (size_t)nt * 256 * 2 * H_ + s * 64, 2 * H_,
                          g_fp + (size_t)s * B_ * H_ + nt * 256, H_, 64, 0, sm);
            }
        }
        gbar(target, -1);

        // ---- P4: score (256 units of (b, 128-n chunk)), bf16 keys, queue 2 ----
        for (;;) {
            int u = qfetch(2, &s_u);
            if (u >= B_ * 4) break;
            int b = u >> 2, c = u & 3;
            for (int j = tid; j < H_; j += NTHR) {
                float a = 0.f;
#pragma unroll
                for (int s = 0; s < SQ; s++) a += g_qp[((size_t)s * B_ + b) * H_ + j];
                sm[j] = a;
                sm[H_ + j] = v_att[j];
            }
            __syncthreads();
            int w = tid >> 5, lane = tid & 31;
            for (int i = 0; i < 8; i++) {
                int n = c * 128 + w * 8 + i;
                const uint4* kp = (const uint4*)(g_keysb + (size_t)(b * N_ + n) * H_);
                float acc = 0.f;
#pragma unroll
                for (int j2 = 0; j2 < 4; j2++) {
                    uint4 kv = kp[lane + 32 * j2];
                    int c8 = (lane + 32 * j2) << 3;
                    float4 q0 = *(const float4*)(sm + c8);
                    float4 q1 = *(const float4*)(sm + c8 + 4);
                    float4 v0 = *(const float4*)(sm + H_ + c8);
                    float4 v1 = *(const float4*)(sm + H_ + c8 + 4);
                    acc += v0.x * tanh_fast(q0.x + __uint_as_float(kv.x << 16));
                    acc += v0.y * tanh_fast(q0.y + __uint_as_float(kv.x & 0xFFFF0000u));
                    acc += v0.z * tanh_fast(q0.z + __uint_as_float(kv.y << 16));
                    acc += v0.w * tanh_fast(q0.w + __uint_as_float(kv.y & 0xFFFF0000u));
                    acc += v1.x * tanh_fast(q1.x + __uint_as_float(kv.z << 16));
                    acc += v1.y * tanh_fast(q1.y + __uint_as_float(kv.z & 0xFFFF0000u));
                    acc += v1.z * tanh_fast(q1.z + __uint_as_float(kv.w << 16));
                    acc += v1.w * tanh_fast(q1.w + __uint_as_float(kv.w & 0xFFFF0000u));
                }
#pragma unroll
                for (int o = 16; o; o >>= 1) acc += __shfl_xor_sync(0xffffffffu, acc, o);
                if (lane == 0) {
                    float mk = vmask[b * N_ + n];
                    g_score[b * N_ + n] = (mk > 0.f) ? acc : -1e9f;
                }
            }
        }
        gbar(target, 2);

        // ---- P5: softmax (one b per CTA) ----
        if (bid < B_) {
            int b = bid;
            int w = tid >> 5, lane = tid & 31;
            float s = g_score[b * N_ + tid];
            float m = s;
#pragma unroll
            for (int o = 16; o; o >>= 1) m = fmaxf(m, __shfl_xor_sync(0xffffffffu, m, o));
            if (lane == 0) red[w] = m;
            __syncthreads();
            float M = red[0];
#pragma unroll
            for (int i = 1; i < 16; i++) M = fmaxf(M, red[i]);
            float p = expf(s - M);
            float ss = p;
#pragma unroll
            for (int o = 16; o; o >>= 1) ss += __shfl_xor_sync(0xffffffffu, ss, o);
            if (lane == 0) red[16 + w] = ss;
            __syncthreads();
            float Z = red[16];
#pragma unroll
            for (int i = 1; i < 16; i++) Z += red[16 + i];
            float a = p / Z;
            g_attn[b * N_ + tid] = a;
            attn_out[((size_t)b * L_ + t) * N_ + tid] = a;
        }
        gbar(target, -1);

        // ---- P6: context from bf16 value (one b per CTA, thread = bf162 h-pair) ----
        if (bid < B_) {
            int b = bid;
            sm[tid] = g_attn[b * N_ + tid];
            __syncthreads();
            const __nv_bfloat162* vp = (const __nv_bfloat162*)(g_valb + (size_t)b * N_ * H_) + tid;
            float a0 = 0.f, a1 = 0.f;
#pragma unroll 8
            for (int n = 0; n < N_; n++) {
                float2 f = __bfloat1622float2(vp[(size_t)n * (H_ / 2)]);
                float wv = sm[n];
                a0 += wv * f.x;
                a1 += wv * f.y;
            }
            g_xf[b * 2 * H_ + H_ + 2 * tid]     = a0;
            g_xf[b * 2 * H_ + H_ + 2 * tid + 1] = a1;
        }
        gbar(target, -1);

        // ---- P7: final ctx-half (64 units, Kc=64), static ----
        if (bid < 64) {
            int nt = bid & 3, s16 = bid >> 2;
            int k0 = H_ + s16 * 64;
            gemm_tile(g_xf + k0, 2 * H_,
                      Wm + (size_t)nt * 256 * 2 * H_ + k0, 2 * H_,
                      g_fp + (size_t)(16 + s16) * B_ * H_ + nt * 256, H_, 64, 0, sm);
        }
        gbar(target, -1);

        // ---- P8: final elementwise ----
        {
            int i = bid * NTHR + tid;
            if (i < B_ * H_) {
                int b = i >> 10, j = i & 1023;
                float a = bm[j];
#pragma unroll
                for (int s = 0; s < SFTOT; s++) a += g_fp[((size_t)s * B_ + b) * H_ + j];
                float y = tanhf(a);
                out[((size_t)b * L_ + t) * H_ + j] = y;
                g_h[i] = y;
            }
        }
        gbar(target, -1);
    }
}

// ---------------- launch: ONE graph node ----------------
extern "C" void kernel_launch(void* const* d_in, const int* in_sizes, int n_in,
                              void* d_out, int out_size) {
    const float* emb    = (const float*)d_in[0];
    const float* value  = (const float*)d_in[1];
    const float* vmask  = (const float*)d_in[2];
    const float* state  = (const float*)d_in[3];
    const float* W_ih   = (const float*)d_in[4];
    const float* b_ih   = (const float*)d_in[5];
    const float* W_hh   = (const float*)d_in[6];
    const float* b_hh   = (const float*)d_in[7];
    const float* Wq     = (const float*)d_in[8];
    const float* Wk     = (const float*)d_in[9];
    const float* v_att  = (const float*)d_in[10];
    const float* Wm     = (const float*)d_in[11];
    const float* bm     = (const float*)d_in[12];

    float* out      = (float*)d_out;                 // outputs: B x L x H
    float* attn_out = out + (size_t)B_ * L_ * H_;    // attns:   B x L x N

    decoder_all<<<NBLK, NTHR>>>(emb, value, vmask, state, W_ih, b_ih, W_hh, b_hh,
                                Wq, Wk, v_att, Wm, bm, out, attn_out);
}

// round 7
// speedup vs baseline: 1.8211x; 1.0808x over previous
#include <cuda_runtime.h>
#include <cuda_bf16.h>
#include <math.h>

#define B_ 64
#define L_ 128
#define E_ 512
#define N_ 512
#define H_ 1024
#define G3 3072
#define KA 1536
#define NBLK 148
#define NTHR 512

#define S1 16      /* splits for gx-h / gh (Kc=64) */
#define SQ 16      /* q splits (Kc=64) */
#define SFTOT 32   /* final splits: 16 rnn + 16 ctx, Kc=64 */

// ---------------- device scratch (static, no allocations) ----------------
__device__ __nv_bfloat16 g_keysb[(size_t)B_ * N_ * H_];  // 67 MB
__device__ __nv_bfloat16 g_valb[(size_t)B_ * N_ * H_];   // 67 MB
__device__ float g_gxe[(size_t)B_ * L_ * G3];            // 100 MB
__device__ float g_h[B_ * H_];
__device__ float g_xf[B_ * 2 * H_];                      // [rnn | ctx]
__device__ float g_score[B_ * N_];
__device__ float g_gxp[(size_t)S1 * B_ * G3];
__device__ float g_ghp[(size_t)S1 * B_ * G3];
__device__ float g_qp[(size_t)SQ * B_ * H_];
__device__ float g_fp[(size_t)SFTOT * B_ * H_];
__device__ unsigned g_cnt;      // barrier arrivals (returns to 0)
__device__ unsigned g_gen;      // barrier generation (monotonic)
__device__ unsigned g_q[4];     // work queues (reset by barrier winner)
__device__ unsigned g_bc[B_];   // per-b score-half counters (monotonic; parity used)

__device__ __forceinline__ float tanh_fast(float x) {
    float y;
    asm("tanh.approx.f32 %0, %1;" : "=f"(y) : "f"(x));
    return y;
}

// ---------------- grid barrier; winner optionally resets a queue ----------------
__device__ __forceinline__ void gbar(unsigned& target, int resetq) {
    __syncthreads();
    if (threadIdx.x == 0) {
        __threadfence();
        if (atomicAdd(&g_cnt, 1u) == (unsigned)NBLK - 1u) {
            atomicExch(&g_cnt, 0u);
            if (resetq >= 0) atomicExch(&g_q[resetq], 0u);
            __threadfence();
            atomicAdd(&g_gen, 1u);
        } else {
            while ((int)(*(volatile unsigned*)&g_gen - target) < 0) __nanosleep(32);
        }
        target++;
    }
    __syncthreads();
}

__device__ __forceinline__ int qfetch(int c, int* s_u) {
    __syncthreads();
    if (threadIdx.x == 0) *s_u = (int)atomicAdd(&g_q[c], 1u);
    __syncthreads();
    return *s_u;
}

// ---------------- 64(M) x 128(N) x Kc SGEMM tile (fp32), double-buffered ------
__device__ __forceinline__ void gemm_tile128(
    const float* __restrict__ Ap, int lda,
    const float* __restrict__ Wp, int ldw,
    float* __restrict__ Co, int ldc, int Kc, float* sm)
{
    const int tid = threadIdx.x;
    const int am = tid >> 3, ak = (tid & 7) << 1;
    const int wn = tid >> 2, wk = (tid & 3) << 2;
    const int tx = tid & 31, ty = tid >> 5;
    const int nkt = Kc >> 4;

    float acc[4][4] = {};
    float2 areg = *(const float2*)(Ap + (size_t)am * lda + ak);
    float4 wreg = *(const float4*)(Wp + (size_t)wn * ldw + wk);

    __syncthreads();
    for (int kt = 0; kt < nkt; kt++) {
        float* As = sm + (kt & 1) * 3200;
        float* Ws = As + 1088;
        As[(ak + 0) * 68 + am] = areg.x;
        As[(ak + 1) * 68 + am] = areg.y;
        Ws[(wk + 0) * 132 + wn] = wreg.x;
        Ws[(wk + 1) * 132 + wn] = wreg.y;
        Ws[(wk + 2) * 132 + wn] = wreg.z;
        Ws[(wk + 3) * 132 + wn] = wreg.w;
        if (kt + 1 < nkt) {
            areg = *(const float2*)(Ap + (size_t)am * lda + (kt + 1) * 16 + ak);
            wreg = *(const float4*)(Wp + (size_t)wn * ldw + (kt + 1) * 16 + wk);
        }
        __syncthreads();
#pragma unroll
        for (int kk = 0; kk < 16; kk++) {
            float4 a = *(const float4*)(As + kk * 68 + (ty << 2));
            float4 w = *(const float4*)(Ws + kk * 132 + (tx << 2));
            acc[0][0] += a.x * w.x; acc[0][1] += a.x * w.y; acc[0][2] += a.x * w.z; acc[0][3] += a.x * w.w;
            acc[1][0] += a.y * w.x; acc[1][1] += a.y * w.y; acc[1][2] += a.y * w.z; acc[1][3] += a.y * w.w;
            acc[2][0] += a.z * w.x; acc[2][1] += a.z * w.y; acc[2][2] += a.z * w.z; acc[2][3] += a.z * w.w;
            acc[3][0] += a.w * w.x; acc[3][1] += a.w * w.y; acc[3][2] += a.w * w.z; acc[3][3] += a.w * w.w;
        }
    }
#pragma unroll
    for (int i = 0; i < 4; i++) {
        *(float4*)(Co + (size_t)((ty << 2) + i) * ldc + (tx << 2)) =
            make_float4(acc[i][0], acc[i][1], acc[i][2], acc[i][3]);
    }
}

// ---------------- 64(M) x 256(N) x Kc SGEMM tile (phase-0 only) ---------------
__device__ __forceinline__ void gemm_tile256(
    const float* __restrict__ Ap, int lda,
    const float* __restrict__ Wp, int ldw,
    void* Co, int ldc, int Kc, int bf16out, float* sm)
{
    const int tid = threadIdx.x;
    const int am = tid >> 3, ak = (tid & 7) << 1;
    const int wn = tid >> 1, wk = (tid & 1) << 3;
    const int tx = tid & 31, ty = tid >> 5;
    const int nkt = Kc >> 4;

    float acc[4][8] = {};
    float2 areg  = *(const float2*)(Ap + (size_t)am * lda + ak);
    float4 wreg0 = *(const float4*)(Wp + (size_t)wn * ldw + wk);
    float4 wreg1 = *(const float4*)(Wp + (size_t)wn * ldw + wk + 4);

    __syncthreads();
    for (int kt = 0; kt < nkt; kt++) {
        float* As = sm + (kt & 1) * 5248;
        float* Ws = As + 1088;
        As[(ak + 0) * 68 + am] = areg.x;
        As[(ak + 1) * 68 + am] = areg.y;
        Ws[(wk + 0) * 260 + wn] = wreg0.x;
        Ws[(wk + 1) * 260 + wn] = wreg0.y;
        Ws[(wk + 2) * 260 + wn] = wreg0.z;
        Ws[(wk + 3) * 260 + wn] = wreg0.w;
        Ws[(wk + 4) * 260 + wn] = wreg1.x;
        Ws[(wk + 5) * 260 + wn] = wreg1.y;
        Ws[(wk + 6) * 260 + wn] = wreg1.z;
        Ws[(wk + 7) * 260 + wn] = wreg1.w;
        if (kt + 1 < nkt) {
            const float* Ap2 = Ap + (kt + 1) * 16;
            const float* Wp2 = Wp + (kt + 1) * 16;
            areg  = *(const float2*)(Ap2 + (size_t)am * lda + ak);
            wreg0 = *(const float4*)(Wp2 + (size_t)wn * ldw + wk);
            wreg1 = *(const float4*)(Wp2 + (size_t)wn * ldw + wk + 4);
        }
        __syncthreads();
#pragma unroll
        for (int kk = 0; kk < 16; kk++) {
            float4 a  = *(const float4*)(As + kk * 68 + (ty << 2));
            float4 w0 = *(const float4*)(Ws + kk * 260 + (tx << 2));
            float4 w1 = *(const float4*)(Ws + kk * 260 + 128 + (tx << 2));
            acc[0][0] += a.x * w0.x; acc[0][1] += a.x * w0.y; acc[0][2] += a.x * w0.z; acc[0][3] += a.x * w0.w;
            acc[1][0] += a.y * w0.x; acc[1][1] += a.y * w0.y; acc[1][2] += a.y * w0.z; acc[1][3] += a.y * w0.w;
            acc[2][0] += a.z * w0.x; acc[2][1] += a.z * w0.y; acc[2][2] += a.z * w0.z; acc[2][3] += a.z * w0.w;
            acc[3][0] += a.w * w0.x; acc[3][1] += a.w * w0.y; acc[3][2] += a.w * w0.z; acc[3][3] += a.w * w0.w;
            acc[0][4] += a.x * w1.x; acc[0][5] += a.x * w1.y; acc[0][6] += a.x * w1.z; acc[0][7] += a.x * w1.w;
            acc[1][4] += a.y * w1.x; acc[1][5] += a.y * w1.y; acc[1][6] += a.y * w1.z; acc[1][7] += a.y * w1.w;
            acc[2][4] += a.z * w1.x; acc[2][5] += a.z * w1.y; acc[2][6] += a.z * w1.z; acc[2][7] += a.z * w1.w;
            acc[3][4] += a.w * w1.x; acc[3][5] += a.w * w1.y; acc[3][6] += a.w * w1.z; acc[3][7] += a.w * w1.w;
        }
    }
    if (!bf16out) {
        float* C = (float*)Co;
#pragma unroll
        for (int i = 0; i < 4; i++) {
            int row = (ty << 2) + i;
            *(float4*)(C + (size_t)row * ldc + (tx << 2)) =
                make_float4(acc[i][0], acc[i][1], acc[i][2], acc[i][3]);
            *(float4*)(C + (size_t)row * ldc + 128 + (tx << 2)) =
                make_float4(acc[i][4], acc[i][5], acc[i][6], acc[i][7]);
        }
    } else {
        __nv_bfloat16* C = (__nv_bfloat16*)Co;
#pragma unroll
        for (int i = 0; i < 4; i++) {
            int row = (ty << 2) + i;
            __nv_bfloat162* p0 = (__nv_bfloat162*)(C + (size_t)row * ldc + (tx << 2));
            p0[0] = __floats2bfloat162_rn(acc[i][0], acc[i][1]);
            p0[1] = __floats2bfloat162_rn(acc[i][2], acc[i][3]);
            __nv_bfloat162* p1 = (__nv_bfloat162*)(C + (size_t)row * ldc + 128 + (tx << 2));
            p1[0] = __floats2bfloat162_rn(acc[i][4], acc[i][5]);
            p1[1] = __floats2bfloat162_rn(acc[i][6], acc[i][7]);
        }
    }
}

// ---------------- the one persistent kernel ----------------
__global__ __launch_bounds__(NTHR, 1) void decoder_all(
    const float* __restrict__ emb,   const float* __restrict__ value,
    const float* __restrict__ vmask, const float* __restrict__ state,
    const float* __restrict__ W_ih,  const float* __restrict__ b_ih,
    const float* __restrict__ W_hh,  const float* __restrict__ b_hh,
    const float* __restrict__ Wq,    const float* __restrict__ Wk,
    const float* __restrict__ v_att, const float* __restrict__ Wm,
    const float* __restrict__ bm,
    float* __restrict__ out, float* __restrict__ attn_out)
{
    __shared__ float sm[10496];
    __shared__ float red[32];
    __shared__ int   s_u;
    __shared__ int   s_flag;
    const int bid = blockIdx.x, tid = threadIdx.x;
    unsigned target = 0;
    if (tid == 0) target = *(volatile unsigned*)&g_gen + 1u;
    __syncthreads();

    // ================= phase 0: init + valb copy + keys GEMM + gxe GEMM ======
    {
        int i = bid * NTHR + tid;
        if (i < B_ * H_) g_h[i] = state[i];
    }
    {
        const float2* vf = (const float2*)value;
        __nv_bfloat162* vb = (__nv_bfloat162*)g_valb;
        int np = B_ * N_ * H_ / 2;
        for (int i = bid * NTHR + tid; i < np; i += NBLK * NTHR) {
            float2 f = vf[i];
            vb[i] = __floats2bfloat162_rn(f.x, f.y);
        }
    }
    for (;;) {
        int u = qfetch(0, &s_u);
        if (u >= 2048 + 1536) break;
        if (u < 2048) {
            int mt = u >> 2, nt = u & 3;
            gemm_tile256(value + (size_t)mt * 64 * H_, H_,
                         Wk + (size_t)nt * 256 * H_, H_,
                         g_keysb + (size_t)mt * 64 * H_ + nt * 256, H_, H_, 1, sm);
        } else {
            int u2 = u - 2048;
            int mt = u2 / 12, nt = u2 % 12;
            gemm_tile256(emb + (size_t)mt * 64 * E_, E_,
                         W_ih + (size_t)nt * 256 * KA, KA,
                         g_gxe + (size_t)mt * 64 * G3 + nt * 256, G3, E_, 0, sm);
        }
    }
    gbar(target, 0);

    for (int t = 0; t < L_; t++) {
        // ---- P1: gx-h (384) + gh (384) 64x128 tiles, Kc=64, queue 1 ----
        for (;;) {
            int u = qfetch(1, &s_u);
            if (u >= 768) break;
            if (u < 384) {
                int nt = u % 24, s = u / 24;
                gemm_tile128(g_h + s * 64, H_,
                             W_ih + (size_t)nt * 128 * KA + E_ + s * 64, KA,
                             g_gxp + (size_t)s * B_ * G3 + nt * 128, G3, 64, sm);
            } else {
                int u2 = u - 384;
                int nt = u2 % 24, s = u2 / 24;
                gemm_tile128(g_h + s * 64, H_,
                             W_hh + (size_t)nt * 128 * H_ + s * 64, H_,
                             g_ghp + (size_t)s * B_ * G3 + nt * 128, G3, 64, sm);
            }
        }
        gbar(target, 1);

        // ---- P2: GRU elementwise ----
        {
            int i = bid * NTHR + tid;
            if (i < B_ * H_) {
                int b = i >> 10, j = i & 1023;
                const float* ge = &g_gxe[(size_t)(b * L_ + t) * G3];
                float gxr = ge[j], gxz = ge[H_ + j], gxn = ge[2 * H_ + j];
                float ghr = 0.f, ghz = 0.f, ghn = 0.f;
#pragma unroll
                for (int s = 0; s < S1; s++) {
                    const float* p = &g_gxp[((size_t)s * B_ + b) * G3];
                    gxr += p[j]; gxz += p[H_ + j]; gxn += p[2 * H_ + j];
                }
#pragma unroll
                for (int s = 0; s < S1; s++) {
                    const float* p = &g_ghp[((size_t)s * B_ + b) * G3];
                    ghr += p[j]; ghz += p[H_ + j]; ghn += p[2 * H_ + j];
                }
                float r = 1.f / (1.f + expf(-(gxr + b_ih[j]        + ghr + b_hh[j])));
                float z = 1.f / (1.f + expf(-(gxz + b_ih[H_ + j]   + ghz + b_hh[H_ + j])));
                float n = tanhf(gxn + b_ih[2 * H_ + j] + r * (ghn + b_hh[2 * H_ + j]));
                float h = g_h[i];
                g_xf[b * 2 * H_ + j] = (1.f - z) * n + z * h;
            }
        }
        gbar(target, -1);

        // ---- P3: q GEMM, 128 static 64x128 tiles (Kc=64) ----
        if (bid < 128) {
            int s = bid >> 3, nt = bid & 7;
            gemm_tile128(g_xf + s * 64, 2 * H_,
                         Wq + (size_t)nt * 128 * H_ + s * 64, H_,
                         g_qp + (size_t)s * B_ * H_ + nt * 128, H_, 64, sm);
        }
        gbar(target, -1);

        // ---- PA: score halves (128) -> per-b softmax+ctx handoff; + final-rnn (128), queue 2
        for (;;) {
            int u = qfetch(2, &s_u);
            if (u >= 256) break;
            if (u < 128) {
                int b = u >> 1, half = u & 1;
                // stage q (reduced) + v_att in smem
                for (int j = tid; j < H_; j += NTHR) {
                    float a = 0.f;
#pragma unroll
                    for (int s = 0; s < SQ; s++) a += g_qp[((size_t)s * B_ + b) * H_ + j];
                    sm[j] = a;
                    sm[H_ + j] = v_att[j];
                }
                __syncthreads();
                int w = tid >> 5, lane = tid & 31;
                for (int i = 0; i < 16; i++) {
                    int n = half * 256 + w * 16 + i;
                    const uint4* kp = (const uint4*)(g_keysb + (size_t)(b * N_ + n) * H_);
                    float acc = 0.f;
#pragma unroll
                    for (int j2 = 0; j2 < 4; j2++) {
                        uint4 kv = kp[lane + 32 * j2];
                        int c8 = (lane + 32 * j2) << 3;
                        float4 q0 = *(const float4*)(sm + c8);
                        float4 q1 = *(const float4*)(sm + c8 + 4);
                        float4 v0 = *(const float4*)(sm + H_ + c8);
                        float4 v1 = *(const float4*)(sm + H_ + c8 + 4);
                        acc += v0.x * tanh_fast(q0.x + __uint_as_float(kv.x << 16));
                        acc += v0.y * tanh_fast(q0.y + __uint_as_float(kv.x & 0xFFFF0000u));
                        acc += v0.z * tanh_fast(q0.z + __uint_as_float(kv.y << 16));
                        acc += v0.w * tanh_fast(q0.w + __uint_as_float(kv.y & 0xFFFF0000u));
                        acc += v1.x * tanh_fast(q1.x + __uint_as_float(kv.z << 16));
                        acc += v1.y * tanh_fast(q1.y + __uint_as_float(kv.z & 0xFFFF0000u));
                        acc += v1.z * tanh_fast(q1.z + __uint_as_float(kv.w << 16));
                        acc += v1.w * tanh_fast(q1.w + __uint_as_float(kv.w & 0xFFFF0000u));
                    }
#pragma unroll
                    for (int o = 16; o; o >>= 1) acc += __shfl_xor_sync(0xffffffffu, acc, o);
                    if (lane == 0) {
                        float mk = vmask[b * N_ + n];
                        g_score[b * N_ + n] = (mk > 0.f) ? acc : -1e9f;
                    }
                }
                // per-b handoff: second finisher runs softmax + ctx
                __syncthreads();
                if (tid == 0) {
                    __threadfence();
                    unsigned old = atomicAdd(&g_bc[b], 1u);
                    s_flag = (int)(old & 1u);
                }
                __syncthreads();
                if (s_flag) {
                    __threadfence();   // acquire side
                    float s0 = __ldcg(&g_score[b * N_ + tid]);
                    float m = s0;
#pragma unroll
                    for (int o = 16; o; o >>= 1) m = fmaxf(m, __shfl_xor_sync(0xffffffffu, m, o));
                    if (lane == 0) red[w] = m;
                    __syncthreads();
                    float M = red[0];
#pragma unroll
                    for (int i2 = 1; i2 < 16; i2++) M = fmaxf(M, red[i2]);
                    float p = expf(s0 - M);
                    float ss = p;
#pragma unroll
                    for (int o = 16; o; o >>= 1) ss += __shfl_xor_sync(0xffffffffu, ss, o);
                    if (lane == 0) red[16 + w] = ss;
                    __syncthreads();
                    float Z = red[16];
#pragma unroll
                    for (int i2 = 1; i2 < 16; i2++) Z += red[16 + i2];
                    float a = p / Z;
                    attn_out[((size_t)b * L_ + t) * N_ + tid] = a;
                    sm[tid] = a;
                    __syncthreads();
                    // ctx: thread owns h-pair (2*tid, 2*tid+1)
                    const __nv_bfloat162* vp =
                        (const __nv_bfloat162*)(g_valb + (size_t)b * N_ * H_) + tid;
                    float a0 = 0.f, a1 = 0.f;
#pragma unroll 8
                    for (int n = 0; n < N_; n++) {
                        float2 f = __bfloat1622float2(vp[(size_t)n * (H_ / 2)]);
                        float wv = sm[n];
                        a0 += wv * f.x;
                        a1 += wv * f.y;
                    }
                    g_xf[b * 2 * H_ + H_ + 2 * tid]     = a0;
                    g_xf[b * 2 * H_ + H_ + 2 * tid + 1] = a1;
                }
            } else {
                // final-rnn tile: s 0..15, nt 0..7
                int u2 = u - 128;
                int s = u2 >> 3, nt = u2 & 7;
                gemm_tile128(g_xf + s * 64, 2 * H_,
                             Wm + (size_t)nt * 128 * 2 * H_ + s * 64, 2 * H_,
                             g_fp + (size_t)s * B_ * H_ + nt * 128, H_, 64, sm);
            }
        }
        gbar(target, 2);

        // ---- P7: final ctx-half, 128 static tiles (s16 0..15, nt 0..7) ----
        if (bid < 128) {
            int s16 = bid >> 3, nt = bid & 7;
            int k0 = H_ + s16 * 64;
            gemm_tile128(g_xf + k0, 2 * H_,
                         Wm + (size_t)nt * 128 * 2 * H_ + k0, 2 * H_,
                         g_fp + (size_t)(16 + s16) * B_ * H_ + nt * 128, H_, 64, sm);
        }
        gbar(target, -1);

        // ---- P8: final elementwise ----
        {
            int i = bid * NTHR + tid;
            if (i < B_ * H_) {
                int b = i >> 10, j = i & 1023;
                float a = bm[j];
#pragma unroll
                for (int s = 0; s < SFTOT; s++) a += g_fp[((size_t)s * B_ + b) * H_ + j];
                float y = tanhf(a);
                out[((size_t)b * L_ + t) * H_ + j] = y;
                g_h[i] = y;
            }
        }
        gbar(target, -1);
    }
}

// ---------------- launch: ONE graph node ----------------
extern "C" void kernel_launch(void* const* d_in, const int* in_sizes, int n_in,
                              void* d_out, int out_size) {
    const float* emb    = (const float*)d_in[0];
    const float* value  = (const float*)d_in[1];
    const float* vmask  = (const float*)d_in[2];
    const float* state  = (const float*)d_in[3];
    const float* W_ih   = (const float*)d_in[4];
    const float* b_ih   = (const float*)d_in[5];
    const float* W_hh   = (const float*)d_in[6];
    const float* b_hh   = (const float*)d_in[7];
    const float* Wq     = (const float*)d_in[8];
    const float* Wk     = (const float*)d_in[9];
    const float* v_att  = (const float*)d_in[10];
    const float* Wm     = (const float*)d_in[11];
    const float* bm     = (const float*)d_in[12];

    float* out      = (float*)d_out;                 // outputs: B x L x H
    float* attn_out = out + (size_t)B_ * L_ * H_;    // attns:   B x L x N

    decoder_all<<<NBLK, NTHR>>>(emb, value, vmask, state, W_ih, b_ih, W_hh, b_hh,
                                Wq, Wk, v_att, Wm, bm, out, attn_out);
}

// round 8
// speedup vs baseline: 2.1977x; 1.2068x over previous
#include <cuda_runtime.h>
#include <cuda_bf16.h>
#include <math.h>

#define B_ 64
#define L_ 128
#define E_ 512
#define N_ 512
#define H_ 1024
#define G3 3072
#define KA 1536
#define NBLK 148
#define NTHR 512

#define S1 8      /* splits for gx-h / gh (Kc=128) */
#define SQ 16     /* q splits (Kc=64) */
#define SF 16     /* final splits: 8 rnn + 8 ctx (Kc=128) */

// ---------------- device scratch (static, no allocations) ----------------
__device__ __nv_bfloat16 g_keysb[(size_t)B_ * N_ * H_];  // 67 MB
__device__ __nv_bfloat16 g_valb[(size_t)B_ * N_ * H_];   // 67 MB
__device__ float g_gxe[(size_t)B_ * L_ * G3];            // 100 MB
__device__ float g_h[B_ * H_];
__device__ float g_xf[B_ * 2 * H_];                      // [rnn | ctx]
__device__ float g_score[B_ * N_];
__device__ float g_gxp[(size_t)S1 * B_ * G3];
__device__ float g_ghp[(size_t)S1 * B_ * G3];
__device__ float g_qp[(size_t)SQ * B_ * H_];
__device__ float g_fp[(size_t)SF * B_ * H_];
__device__ unsigned g_cnt2[37 * 64];   // group counters, 256B apart (monotone)
__device__ unsigned g_cntr;            // root counter (monotone)
__device__ unsigned g_gen;             // generation (monotone)
__device__ unsigned g_q[4];            // work queues (reset by barrier winner)
__device__ unsigned g_bc[B_];          // per-b score-half counters (monotone)

__device__ __forceinline__ float tanh_fast(float x) {
    float y;
    asm("tanh.approx.f32 %0, %1;" : "=f"(y) : "f"(x));
    return y;
}

// ---------------- 2-level grid barrier ----------------
__device__ __forceinline__ void gbar(unsigned& target, int resetq) {
    __syncthreads();
    if (threadIdx.x == 0) {
        __threadfence();
        unsigned v = atomicAdd(&g_cnt2[(blockIdx.x >> 2) * 64], 1u);
        if ((v & 3u) == 3u) {                       // last of 4 in group
            unsigned r = atomicAdd(&g_cntr, 1u);
            if (r % 37u == 36u) {                   // last group
                if (resetq >= 0) atomicExch(&g_q[resetq], 0u);
                __threadfence();
                atomicAdd(&g_gen, 1u);
            }
        }
        while ((int)(*(volatile unsigned*)&g_gen - target) < 0) { }
        target++;
    }
    __syncthreads();
}

__device__ __forceinline__ int qfetch(int c, int* s_u) {
    __syncthreads();
    if (threadIdx.x == 0) *s_u = (int)atomicAdd(&g_q[c], 1u);
    __syncthreads();
    return *s_u;
}

// ---------------- bf16 split helpers ----------------
__device__ __forceinline__ void split2(float2 v, unsigned& hi, unsigned& lo) {
    __nv_bfloat16 hx = __float2bfloat16_rn(v.x);
    __nv_bfloat16 hy = __float2bfloat16_rn(v.y);
    float rx = v.x - __bfloat162float(hx);
    float ry = v.y - __bfloat162float(hy);
    __nv_bfloat162 h2; h2.x = hx; h2.y = hy;
    __nv_bfloat162 l2 = __floats2bfloat162_rn(rx, ry);
    hi = *(unsigned*)&h2;
    lo = *(unsigned*)&l2;
}

#define MMA16816(c0,c1,c2,c3,a0,a1,a2,a3,b0,b1) \
    asm volatile("mma.sync.aligned.m16n8k16.row.col.f32.bf16.bf16.f32 " \
        "{%0,%1,%2,%3},{%4,%5,%6,%7},{%8,%9},{%0,%1,%2,%3};" \
        : "+f"(c0),"+f"(c1),"+f"(c2),"+f"(c3) \
        : "r"(a0),"r"(a1),"r"(a2),"r"(a3),"r"(b0),"r"(b1))

// ---------------- 64(M) x 128(N) x Kc GEMM tile via split-bf16 MMA ------------
// C[m][n] = sum_k Ap[m*lda+k] * Wp[n*ldw+k]   (fp32-accurate: hh + hl + lh)
// smem buffer layout (words, per parity): [Ah 64x12][Al 64x12][Wh 128x12][Wl 128x12]
__device__ __forceinline__ void gemm_mma(
    const float* __restrict__ Ap, int lda,
    const float* __restrict__ Wp, int ldw,
    void* Co, int ldc, int Kc, int bf16out, float* smf)
{
    unsigned* smu = (unsigned*)smf;
    const int tid = threadIdx.x;
    const int lane = tid & 31;
    const int g = lane >> 2, tg = lane & 3;
    const int wm = ((tid >> 5) >> 2) << 4;   // warp m-offset: 0/16/32/48
    const int wn = ((tid >> 5) & 3) << 5;    // warp n-offset: 0/32/64/96
    const int nkt = Kc >> 4;
    const int arow = tid >> 3, akp = tid & 7;

    float acc[4][4] = {};

    float2 apf  = *(const float2*)(Ap + (size_t)arow * lda + 2 * akp);
    float2 wpf0 = *(const float2*)(Wp + (size_t)arow * ldw + 2 * akp);
    float2 wpf1 = *(const float2*)(Wp + (size_t)(arow + 64) * ldw + 2 * akp);

    __syncthreads();   // protect smem from previous use
    for (int kt = 0; kt < nkt; kt++) {
        unsigned* buf = smu + (kt & 1) * 4608;
        unsigned hi, lo;
        split2(apf, hi, lo);
        buf[arow * 12 + akp] = hi;
        buf[768 + arow * 12 + akp] = lo;
        split2(wpf0, hi, lo);
        buf[1536 + arow * 12 + akp] = hi;
        buf[3072 + arow * 12 + akp] = lo;
        split2(wpf1, hi, lo);
        buf[1536 + (arow + 64) * 12 + akp] = hi;
        buf[3072 + (arow + 64) * 12 + akp] = lo;
        if (kt + 1 < nkt) {
            const float* A2 = Ap + (kt + 1) * 16;
            const float* W2 = Wp + (kt + 1) * 16;
            apf  = *(const float2*)(A2 + (size_t)arow * lda + 2 * akp);
            wpf0 = *(const float2*)(W2 + (size_t)arow * ldw + 2 * akp);
            wpf1 = *(const float2*)(W2 + (size_t)(arow + 64) * ldw + 2 * akp);
        }
        __syncthreads();
        unsigned a0h = buf[(wm + g) * 12 + tg];
        unsigned a1h = buf[(wm + g + 8) * 12 + tg];
        unsigned a2h = buf[(wm + g) * 12 + tg + 4];
        unsigned a3h = buf[(wm + g + 8) * 12 + tg + 4];
        unsigned a0l = buf[768 + (wm + g) * 12 + tg];
        unsigned a1l = buf[768 + (wm + g + 8) * 12 + tg];
        unsigned a2l = buf[768 + (wm + g) * 12 + tg + 4];
        unsigned a3l = buf[768 + (wm + g + 8) * 12 + tg + 4];
#pragma unroll
        for (int blk = 0; blk < 4; blk++) {
            int r = (wn + blk * 8 + g) * 12;
            unsigned b0h = buf[1536 + r + tg];
            unsigned b1h = buf[1536 + r + tg + 4];
            unsigned b0l = buf[3072 + r + tg];
            unsigned b1l = buf[3072 + r + tg + 4];
            MMA16816(acc[blk][0], acc[blk][1], acc[blk][2], acc[blk][3],
                     a0h, a1h, a2h, a3h, b0h, b1h);
            MMA16816(acc[blk][0], acc[blk][1], acc[blk][2], acc[blk][3],
                     a0h, a1h, a2h, a3h, b0l, b1l);
            MMA16816(acc[blk][0], acc[blk][1], acc[blk][2], acc[blk][3],
                     a0l, a1l, a2l, a3l, b0h, b1h);
        }
    }
    // D layout: d0=(g,2tg) d1=(g,2tg+1) d2=(g+8,2tg) d3=(g+8,2tg+1) per n8 block
    if (!bf16out) {
        float* C = (float*)Co;
#pragma unroll
        for (int blk = 0; blk < 4; blk++) {
            int col = wn + blk * 8 + 2 * tg;
            *(float2*)(C + (size_t)(wm + g) * ldc + col) =
                make_float2(acc[blk][0], acc[blk][1]);
            *(float2*)(C + (size_t)(wm + g + 8) * ldc + col) =
                make_float2(acc[blk][2], acc[blk][3]);
        }
    } else {
        __nv_bfloat16* C = (__nv_bfloat16*)Co;
#pragma unroll
        for (int blk = 0; blk < 4; blk++) {
            int col = wn + blk * 8 + 2 * tg;
            *(__nv_bfloat162*)(C + (size_t)(wm + g) * ldc + col) =
                __floats2bfloat162_rn(acc[blk][0], acc[blk][1]);
            *(__nv_bfloat162*)(C + (size_t)(wm + g + 8) * ldc + col) =
                __floats2bfloat162_rn(acc[blk][2], acc[blk][3]);
        }
    }
}

// ---------------- the one persistent kernel ----------------
__global__ __launch_bounds__(NTHR, 1) void decoder_all(
    const float* __restrict__ emb,   const float* __restrict__ value,
    const float* __restrict__ vmask, const float* __restrict__ state,
    const float* __restrict__ W_ih,  const float* __restrict__ b_ih,
    const float* __restrict__ W_hh,  const float* __restrict__ b_hh,
    const float* __restrict__ Wq,    const float* __restrict__ Wk,
    const float* __restrict__ v_att, const float* __restrict__ Wm,
    const float* __restrict__ bm,
    float* __restrict__ out, float* __restrict__ attn_out)
{
    __shared__ float sm[9216];   // 36 KB: 2x4608-word mma buffers; reused by score/ctx
    __shared__ float red[32];
    __shared__ int   s_u;
    __shared__ int   s_flag;
    const int bid = blockIdx.x, tid = threadIdx.x;
    unsigned target = 0;
    if (tid == 0) target = *(volatile unsigned*)&g_gen + 1u;
    __syncthreads();

    // ================= phase 0: init + valb copy + keys GEMM + gxe GEMM ======
    {
        int i = bid * NTHR + tid;
        if (i < B_ * H_) g_h[i] = state[i];
    }
    {
        const float2* vf = (const float2*)value;
        __nv_bfloat162* vb = (__nv_bfloat162*)g_valb;
        int np = B_ * N_ * H_ / 2;
        for (int i = bid * NTHR + tid; i < np; i += NBLK * NTHR) {
            float2 f = vf[i];
            vb[i] = __floats2bfloat162_rn(f.x, f.y);
        }
    }
    for (;;) {
        int u = qfetch(0, &s_u);
        if (u >= 4096 + 3072) break;
        if (u < 4096) {
            // keys: M=B*N (mt 0..511), Nn=H (nt 0..7), K=H (no split)
            int mt = u >> 3, nt = u & 7;
            gemm_mma(value + (size_t)mt * 64 * H_, H_,
                     Wk + (size_t)nt * 128 * H_, H_,
                     g_keysb + (size_t)mt * 64 * H_ + nt * 128, H_, H_, 1, sm);
        } else {
            // gxe: M=B*L (mt 0..127), Nn=G3 (nt 0..23), K=E
            int u2 = u - 4096;
            int mt = u2 / 24, nt = u2 % 24;
            gemm_mma(emb + (size_t)mt * 64 * E_, E_,
                     W_ih + (size_t)nt * 128 * KA, KA,
                     g_gxe + (size_t)mt * 64 * G3 + nt * 128, G3, E_, 0, sm);
        }
    }
    gbar(target, 0);

    for (int t = 0; t < L_; t++) {
        // ---- P1: gx-h (192) + gh (192), Kc=128, queue 1 ----
        for (;;) {
            int u = qfetch(1, &s_u);
            if (u >= 384) break;
            if (u < 192) {
                int nt = u % 24, s = u / 24;
                gemm_mma(g_h + s * 128, H_,
                         W_ih + (size_t)nt * 128 * KA + E_ + s * 128, KA,
                         g_gxp + (size_t)s * B_ * G3 + nt * 128, G3, 128, 0, sm);
            } else {
                int u2 = u - 192;
                int nt = u2 % 24, s = u2 / 24;
                gemm_mma(g_h + s * 128, H_,
                         W_hh + (size_t)nt * 128 * H_ + s * 128, H_,
                         g_ghp + (size_t)s * B_ * G3 + nt * 128, G3, 128, 0, sm);
            }
        }
        gbar(target, 1);

        // ---- P2: GRU elementwise ----
        {
            int i = bid * NTHR + tid;
            if (i < B_ * H_) {
                int b = i >> 10, j = i & 1023;
                const float* ge = &g_gxe[(size_t)(b * L_ + t) * G3];
                float gxr = ge[j], gxz = ge[H_ + j], gxn = ge[2 * H_ + j];
                float ghr = 0.f, ghz = 0.f, ghn = 0.f;
#pragma unroll
                for (int s = 0; s < S1; s++) {
                    const float* p = &g_gxp[((size_t)s * B_ + b) * G3];
                    gxr += p[j]; gxz += p[H_ + j]; gxn += p[2 * H_ + j];
                }
#pragma unroll
                for (int s = 0; s < S1; s++) {
                    const float* p = &g_ghp[((size_t)s * B_ + b) * G3];
                    ghr += p[j]; ghz += p[H_ + j]; ghn += p[2 * H_ + j];
                }
                float r = 1.f / (1.f + expf(-(gxr + b_ih[j]        + ghr + b_hh[j])));
                float z = 1.f / (1.f + expf(-(gxz + b_ih[H_ + j]   + ghz + b_hh[H_ + j])));
                float n = tanhf(gxn + b_ih[2 * H_ + j] + r * (ghn + b_hh[2 * H_ + j]));
                float h = g_h[i];
                g_xf[b * 2 * H_ + j] = (1.f - z) * n + z * h;
            }
        }
        gbar(target, -1);

        // ---- P3: q GEMM, 128 static tiles (SQ=16, Kc=64) ----
        if (bid < 128) {
            int s = bid >> 3, nt = bid & 7;
            gemm_mma(g_xf + s * 64, 2 * H_,
                     Wq + (size_t)nt * 128 * H_ + s * 64, H_,
                     g_qp + (size_t)s * B_ * H_ + nt * 128, H_, 64, 0, sm);
        }
        gbar(target, -1);

        // ---- PA: score halves (128) w/ per-b softmax+ctx handoff; + final-rnn (64)
        for (;;) {
            int u = qfetch(2, &s_u);
            if (u >= 192) break;
            if (u < 128) {
                int b = u >> 1, half = u & 1;
                for (int j = tid; j < H_; j += NTHR) {
                    float a = 0.f;
#pragma unroll
                    for (int s = 0; s < SQ; s++) a += g_qp[((size_t)s * B_ + b) * H_ + j];
                    sm[j] = a;
                    sm[H_ + j] = v_att[j];
                }
                __syncthreads();
                int w = tid >> 5, lane = tid & 31;
                for (int i = 0; i < 16; i++) {
                    int n = half * 256 + w * 16 + i;
                    const uint4* kp = (const uint4*)(g_keysb + (size_t)(b * N_ + n) * H_);
                    float acc = 0.f;
#pragma unroll
                    for (int j2 = 0; j2 < 4; j2++) {
                        uint4 kv = kp[lane + 32 * j2];
                        int c8 = (lane + 32 * j2) << 3;
                        float4 q0 = *(const float4*)(sm + c8);
                        float4 q1 = *(const float4*)(sm + c8 + 4);
                        float4 v0 = *(const float4*)(sm + H_ + c8);
                        float4 v1 = *(const float4*)(sm + H_ + c8 + 4);
                        acc += v0.x * tanh_fast(q0.x + __uint_as_float(kv.x << 16));
                        acc += v0.y * tanh_fast(q0.y + __uint_as_float(kv.x & 0xFFFF0000u));
                        acc += v0.z * tanh_fast(q0.z + __uint_as_float(kv.y << 16));
                        acc += v0.w * tanh_fast(q0.w + __uint_as_float(kv.y & 0xFFFF0000u));
                        acc += v1.x * tanh_fast(q1.x + __uint_as_float(kv.z << 16));
                        acc += v1.y * tanh_fast(q1.y + __uint_as_float(kv.z & 0xFFFF0000u));
                        acc += v1.z * tanh_fast(q1.z + __uint_as_float(kv.w << 16));
                        acc += v1.w * tanh_fast(q1.w + __uint_as_float(kv.w & 0xFFFF0000u));
                    }
#pragma unroll
                    for (int o = 16; o; o >>= 1) acc += __shfl_xor_sync(0xffffffffu, acc, o);
                    if (lane == 0) {
                        float mk = vmask[b * N_ + n];
                        g_score[b * N_ + n] = (mk > 0.f) ? acc : -1e9f;
                    }
                }
                __syncthreads();
                if (tid == 0) {
                    __threadfence();
                    unsigned old = atomicAdd(&g_bc[b], 1u);
                    s_flag = (int)(old & 1u);
                }
                __syncthreads();
                if (s_flag) {
                    __threadfence();
                    float s0 = __ldcg(&g_score[b * N_ + tid]);
                    float m = s0;
#pragma unroll
                    for (int o = 16; o; o >>= 1) m = fmaxf(m, __shfl_xor_sync(0xffffffffu, m, o));
                    if (lane == 0) red[w] = m;
                    __syncthreads();
                    float M = red[0];
#pragma unroll
                    for (int i2 = 1; i2 < 16; i2++) M = fmaxf(M, red[i2]);
                    float p = expf(s0 - M);
                    float ss = p;
#pragma unroll
                    for (int o = 16; o; o >>= 1) ss += __shfl_xor_sync(0xffffffffu, ss, o);
                    if (lane == 0) red[16 + w] = ss;
                    __syncthreads();
                    float Z = red[16];
#pragma unroll
                    for (int i2 = 1; i2 < 16; i2++) Z += red[16 + i2];
                    float a = p / Z;
                    attn_out[((size_t)b * L_ + t) * N_ + tid] = a;
                    sm[tid] = a;
                    __syncthreads();
                    const __nv_bfloat162* vp =
                        (const __nv_bfloat162*)(g_valb + (size_t)b * N_ * H_) + tid;
                    float a0 = 0.f, a1 = 0.f;
#pragma unroll 8
                    for (int n = 0; n < N_; n++) {
                        float2 f = __bfloat1622float2(vp[(size_t)n * (H_ / 2)]);
                        float wv = sm[n];
                        a0 += wv * f.x;
                        a1 += wv * f.y;
                    }
                    g_xf[b * 2 * H_ + H_ + 2 * tid]     = a0;
                    g_xf[b * 2 * H_ + H_ + 2 * tid + 1] = a1;
                }
            } else {
                // final-rnn: s 0..7, nt 0..7, Kc=128
                int u2 = u - 128;
                int s = u2 >> 3, nt = u2 & 7;
                gemm_mma(g_xf + s * 128, 2 * H_,
                         Wm + (size_t)nt * 128 * 2 * H_ + s * 128, 2 * H_,
                         g_fp + (size_t)s * B_ * H_ + nt * 128, H_, 128, 0, sm);
            }
        }
        gbar(target, 2);

        // ---- P7: final ctx-half, 64 static tiles (s 0..7, nt 0..7, Kc=128) ----
        if (bid < 64) {
            int s = bid >> 3, nt = bid & 7;
            int k0 = H_ + s * 128;
            gemm_mma(g_xf + k0, 2 * H_,
                     Wm + (size_t)nt * 128 * 2 * H_ + k0, 2 * H_,
                     g_fp + (size_t)(8 + s) * B_ * H_ + nt * 128, H_, 128, 0, sm);
        }
        gbar(target, -1);

        // ---- P8: final elementwise ----
        {
            int i = bid * NTHR + tid;
            if (i < B_ * H_) {
                int b = i >> 10, j = i & 1023;
                float a = bm[j];
#pragma unroll
                for (int s = 0; s < SF; s++) a += g_fp[((size_t)s * B_ + b) * H_ + j];
                float y = tanhf(a);
                out[((size_t)b * L_ + t) * H_ + j] = y;
                g_h[i] = y;
            }
        }
        gbar(target, -1);
    }
}

// ---------------- launch: ONE graph node ----------------
extern "C" void kernel_launch(void* const* d_in, const int* in_sizes, int n_in,
                              void* d_out, int out_size) {
    const float* emb    = (const float*)d_in[0];
    const float* value  = (const float*)d_in[1];
    const float* vmask  = (const float*)d_in[2];
    const float* state  = (const float*)d_in[3];
    const float* W_ih   = (const float*)d_in[4];
    const float* b_ih   = (const float*)d_in[5];
    const float* W_hh   = (const float*)d_in[6];
    const float* b_hh   = (const float*)d_in[7];
    const float* Wq     = (const float*)d_in[8];
    const float* Wk     = (const float*)d_in[9];
    const float* v_att  = (const float*)d_in[10];
    const float* Wm     = (const float*)d_in[11];
    const float* bm     = (const float*)d_in[12];

    float* out      = (float*)d_out;                 // outputs: B x L x H
    float* attn_out = out + (size_t)B_ * L_ * H_;    // attns:   B x L x N

    decoder_all<<<NBLK, NTHR>>>(emb, value, vmask, state, W_ih, b_ih, W_hh, b_hh,
                                Wq, Wk, v_att, Wm, bm, out, attn_out);
}